// round 1
// baseline (speedup 1.0000x reference)
#include <cuda_runtime.h>
#include <math.h>

// ---------------------------------------------------------------------------
// Problem constants: B=2, N=2048, E=QK=V=2048, M=4096, H=16, dk=dv=128
// ---------------------------------------------------------------------------
#define BN_ROWS   4096          // B*N
#define EDIM      2048
#define MDIM      4096
#define HEADS     16
#define DHEAD     128

// Scratch (allocation-free rule: static __device__ arrays)
static __device__ float g_q[8388608];     // [B*N, 2048] = q
static __device__ float g_gate[8388608];  // [B*N, 2048] = silu(x Wg^T)
static __device__ float g_attn[8388608];  // [B*N, 2048] = (attn out) * gate

__device__ __forceinline__ float silu_f(float x) {
    return x / (1.0f + __expf(-x));
}

// ---------------------------------------------------------------------------
// TN GEMM: C[m][n] = act( sum_k A[m*K+k] * Bw[n*K+k] )
// BM=BN=128, BK=16, 256 threads, 8x8 register tile (split 4+4 across 64-col
// halves so LDS.128 phases are conflict-free).
// ---------------------------------------------------------------------------
template<bool SILU>
__global__ __launch_bounds__(256, 2)
void gemm_tn(const float* __restrict__ A, const float* __restrict__ Bw,
             float* __restrict__ C, int Mrows, int Ncols, int K) {
    __shared__ float As[16][132];
    __shared__ float Bs[16][132];
    const int tid = threadIdx.x;
    const int tx = tid & 15, ty = tid >> 4;
    const int m0 = blockIdx.y * 128, n0 = blockIdx.x * 128;

    const float* Ab = A + (size_t)m0 * K;
    const float* Bb = Bw + (size_t)n0 * K;

    float acc[8][8];
#pragma unroll
    for (int i = 0; i < 8; i++)
#pragma unroll
        for (int j = 0; j < 8; j++) acc[i][j] = 0.0f;

    for (int k0 = 0; k0 < K; k0 += 16) {
#pragma unroll
        for (int f = tid; f < 512; f += 256) {
            int row = f >> 2, kc = (f & 3) * 4;
            float4 va = *(const float4*)(Ab + (size_t)row * K + k0 + kc);
            As[kc + 0][row] = va.x; As[kc + 1][row] = va.y;
            As[kc + 2][row] = va.z; As[kc + 3][row] = va.w;
            float4 vb = *(const float4*)(Bb + (size_t)row * K + k0 + kc);
            Bs[kc + 0][row] = vb.x; Bs[kc + 1][row] = vb.y;
            Bs[kc + 2][row] = vb.z; Bs[kc + 3][row] = vb.w;
        }
        __syncthreads();
#pragma unroll
        for (int k = 0; k < 16; k++) {
            float4 a0 = *(const float4*)&As[k][4 * ty];
            float4 a1 = *(const float4*)&As[k][64 + 4 * ty];
            float4 b0 = *(const float4*)&Bs[k][4 * tx];
            float4 b1 = *(const float4*)&Bs[k][64 + 4 * tx];
            float ar[8] = {a0.x, a0.y, a0.z, a0.w, a1.x, a1.y, a1.z, a1.w};
            float br[8] = {b0.x, b0.y, b0.z, b0.w, b1.x, b1.y, b1.z, b1.w};
#pragma unroll
            for (int i = 0; i < 8; i++)
#pragma unroll
                for (int j = 0; j < 8; j++)
                    acc[i][j] += ar[i] * br[j];
        }
        __syncthreads();
    }

#pragma unroll
    for (int ih = 0; ih < 2; ih++)
#pragma unroll
        for (int ii = 0; ii < 4; ii++) {
            int row = m0 + ih * 64 + 4 * ty + ii;
            float* Crow = C + (size_t)row * Ncols + n0;
#pragma unroll
            for (int jh = 0; jh < 2; jh++) {
                float4 w;
                float v0 = acc[ih * 4 + ii][jh * 4 + 0];
                float v1 = acc[ih * 4 + ii][jh * 4 + 1];
                float v2 = acc[ih * 4 + ii][jh * 4 + 2];
                float v3 = acc[ih * 4 + ii][jh * 4 + 3];
                if (SILU) { v0 = silu_f(v0); v1 = silu_f(v1); v2 = silu_f(v2); v3 = silu_f(v3); }
                w.x = v0; w.y = v1; w.z = v2; w.w = v3;
                *(float4*)(Crow + jh * 64 + 4 * tx) = w;
            }
        }
}

// ---------------------------------------------------------------------------
// Fused attention: per CTA one (b, h, 64-row q tile).
//   loop over M in 64-key tiles:
//     s = silu( (q) @ (k*scale)^T )   [64x64]
//     acc += s @ (v*scale)            [64x128]
// epilogue: out = acc * gate  (pre-gated for the final GEMM)
// smem (dynamic, 118784 B): qs[64][132], ks[64][132], vs[64][132], ss[64][68]
// ---------------------------------------------------------------------------
#define ATT_SMEM_FLOATS 29696
#define ATT_SMEM_BYTES  (ATT_SMEM_FLOATS * 4)

__global__ __launch_bounds__(256, 1)
void attn_kernel(const float* __restrict__ q, const float* __restrict__ kw,
                 const float* __restrict__ vw, const float* __restrict__ gate,
                 float* __restrict__ outp) {
    extern __shared__ float sm[];
    float* qs = sm;            // 64*132
    float* ks = sm + 8448;     // 64*132
    float* vs = sm + 16896;    // 64*132
    float* ss = sm + 25344;    // 64*68

    const int tid = threadIdx.x;
    const int tx = tid & 15, ty = tid >> 4;
    const int n0 = blockIdx.x * 64;
    const int h  = blockIdx.y;
    const int b  = blockIdx.z;
    const float SCALE = sqrtf(128.0f);

    const float* qb = q + ((size_t)(b * 2048 + n0)) * 2048 + h * 128;
#pragma unroll
    for (int f = tid; f < 2048; f += 256) {
        int r = f >> 5, c4 = (f & 31) << 2;
        *(float4*)(qs + r * 132 + c4) = *(const float4*)(qb + (size_t)r * 2048 + c4);
    }

    float acc[4][8];
#pragma unroll
    for (int i = 0; i < 4; i++)
#pragma unroll
        for (int j = 0; j < 8; j++) acc[i][j] = 0.0f;

    for (int m0 = 0; m0 < MDIM; m0 += 64) {
        const float* kb = kw + (size_t)m0 * 2048 + h * 128;
        const float* vb = vw + (size_t)m0 * 2048 + h * 128;
        __syncthreads();   // previous iter consumers of ks/vs/ss done (1st iter: no-op)
#pragma unroll
        for (int f = tid; f < 2048; f += 256) {
            int r = f >> 5, c4 = (f & 31) << 2;
            float4 kv = *(const float4*)(kb + (size_t)r * 2048 + c4);
            kv.x *= SCALE; kv.y *= SCALE; kv.z *= SCALE; kv.w *= SCALE;
            *(float4*)(ks + r * 132 + c4) = kv;
            float4 vv = *(const float4*)(vb + (size_t)r * 2048 + c4);
            vv.x *= SCALE; vv.y *= SCALE; vv.z *= SCALE; vv.w *= SCALE;
            *(float4*)(vs + r * 132 + c4) = vv;
        }
        __syncthreads();

        // ---- stage 1: s[64][64] = silu(qs @ ks^T), 4x4 per thread
        float sa[4][4];
#pragma unroll
        for (int i = 0; i < 4; i++)
#pragma unroll
            for (int j = 0; j < 4; j++) sa[i][j] = 0.0f;

#pragma unroll 8
        for (int d4 = 0; d4 < 32; d4++) {
            float4 a[4], bb[4];
#pragma unroll
            for (int i = 0; i < 4; i++)
                a[i] = *(const float4*)(qs + (ty + 16 * i) * 132 + d4 * 4);
#pragma unroll
            for (int j = 0; j < 4; j++)
                bb[j] = *(const float4*)(ks + (tx + 16 * j) * 132 + d4 * 4);
#pragma unroll
            for (int i = 0; i < 4; i++)
#pragma unroll
                for (int j = 0; j < 4; j++)
                    sa[i][j] += a[i].x * bb[j].x + a[i].y * bb[j].y
                              + a[i].z * bb[j].z + a[i].w * bb[j].w;
        }
#pragma unroll
        for (int i = 0; i < 4; i++)
#pragma unroll
            for (int j = 0; j < 4; j++)
                ss[(ty + 16 * i) * 68 + tx + 16 * j] = silu_f(sa[i][j]);
        __syncthreads();

        // ---- stage 2: acc[64][128] += ss @ vs, 4x8 per thread
#pragma unroll 8
        for (int kk = 0; kk < 64; kk++) {
            float s0 = ss[(ty +  0) * 68 + kk];
            float s1 = ss[(ty + 16) * 68 + kk];
            float s2 = ss[(ty + 32) * 68 + kk];
            float s3 = ss[(ty + 48) * 68 + kk];
            float4 v0 = *(const float4*)(vs + kk * 132 + 4 * tx);
            float4 v1 = *(const float4*)(vs + kk * 132 + 64 + 4 * tx);
            acc[0][0] += s0 * v0.x; acc[0][1] += s0 * v0.y; acc[0][2] += s0 * v0.z; acc[0][3] += s0 * v0.w;
            acc[0][4] += s0 * v1.x; acc[0][5] += s0 * v1.y; acc[0][6] += s0 * v1.z; acc[0][7] += s0 * v1.w;
            acc[1][0] += s1 * v0.x; acc[1][1] += s1 * v0.y; acc[1][2] += s1 * v0.z; acc[1][3] += s1 * v0.w;
            acc[1][4] += s1 * v1.x; acc[1][5] += s1 * v1.y; acc[1][6] += s1 * v1.z; acc[1][7] += s1 * v1.w;
            acc[2][0] += s2 * v0.x; acc[2][1] += s2 * v0.y; acc[2][2] += s2 * v0.z; acc[2][3] += s2 * v0.w;
            acc[2][4] += s2 * v1.x; acc[2][5] += s2 * v1.y; acc[2][6] += s2 * v1.z; acc[2][7] += s2 * v1.w;
            acc[3][0] += s3 * v0.x; acc[3][1] += s3 * v0.y; acc[3][2] += s3 * v0.z; acc[3][3] += s3 * v0.w;
            acc[3][4] += s3 * v1.x; acc[3][5] += s3 * v1.y; acc[3][6] += s3 * v1.z; acc[3][7] += s3 * v1.w;
        }
    }

    // ---- epilogue: multiply by gate, write pre-gated attention output
    size_t obase = ((size_t)(b * 2048 + n0)) * 2048 + h * 128;
#pragma unroll
    for (int i = 0; i < 4; i++) {
        int r = ty + 16 * i;
        size_t o = obase + (size_t)r * 2048;
        float4 g0 = *(const float4*)(gate + o + 4 * tx);
        float4 g1 = *(const float4*)(gate + o + 64 + 4 * tx);
        float4 w0, w1;
        w0.x = acc[i][0] * g0.x; w0.y = acc[i][1] * g0.y;
        w0.z = acc[i][2] * g0.z; w0.w = acc[i][3] * g0.w;
        w1.x = acc[i][4] * g1.x; w1.y = acc[i][5] * g1.y;
        w1.z = acc[i][6] * g1.z; w1.w = acc[i][7] * g1.w;
        *(float4*)(outp + o + 4 * tx) = w0;
        *(float4*)(outp + o + 64 + 4 * tx) = w1;
    }
}

// ---------------------------------------------------------------------------
// Launch: q-GEMM, gate-GEMM(silu), fused attention (gate applied), out-GEMM
// ---------------------------------------------------------------------------
extern "C" void kernel_launch(void* const* d_in, const int* in_sizes, int n_in,
                              void* d_out, int out_size) {
    const float* x  = (const float*)d_in[0];
    const float* Wq = (const float*)d_in[1];
    const float* kw = (const float*)d_in[2];
    const float* vw = (const float*)d_in[3];
    const float* Wg = (const float*)d_in[4];
    const float* Wo = (const float*)d_in[5];
    float* out = (float*)d_out;

    float *qp, *gp, *ap;
    cudaGetSymbolAddress((void**)&qp, g_q);
    cudaGetSymbolAddress((void**)&gp, g_gate);
    cudaGetSymbolAddress((void**)&ap, g_attn);

    cudaFuncSetAttribute(attn_kernel, cudaFuncAttributeMaxDynamicSharedMemorySize,
                         ATT_SMEM_BYTES);

    dim3 gemm_grid(EDIM / 128, BN_ROWS / 128);   // (16, 32)
    gemm_tn<false><<<gemm_grid, 256>>>(x, Wq, qp, BN_ROWS, EDIM, EDIM);
    gemm_tn<true ><<<gemm_grid, 256>>>(x, Wg, gp, BN_ROWS, EDIM, EDIM);

    attn_kernel<<<dim3(2048 / 64, HEADS, 2), 256, ATT_SMEM_BYTES>>>(qp, kw, vw, gp, ap);

    gemm_tn<false><<<gemm_grid, 256>>>(ap, Wo, out, BN_ROWS, EDIM, EDIM);
}

// round 3
// speedup vs baseline: 2.8035x; 2.8035x over previous
#include <cuda_runtime.h>
#include <cuda_bf16.h>

typedef unsigned int u32;
typedef unsigned long long u64;
typedef __nv_bfloat16 bf16;

#define SCALE_F 11.313708498984761f   // sqrt(128)

// ---------------- scratch (bf16 hi/lo pairs) ----------------
static __device__ bf16 g_xh[8388608],  g_xl[8388608];
static __device__ bf16 g_wqh[4194304], g_wql[4194304];
static __device__ bf16 g_wgh[4194304], g_wgl[4194304];
static __device__ bf16 g_woh[4194304], g_wol[4194304];
static __device__ bf16 g_kh[8388608],  g_kl[8388608];
static __device__ bf16 g_vth[8388608], g_vtl[8388608];
static __device__ bf16 g_qh[8388608],  g_ql[8388608];
static __device__ bf16 g_gh[8388608],  g_gl[8388608];
static __device__ bf16 g_ah[8388608],  g_al[8388608];

// ---------------- helpers ----------------
__device__ __forceinline__ u32 smem_u32(const void* p) {
    u32 a;
    asm("{ .reg .u64 t; cvta.to.shared.u64 t, %1; cvt.u32.u64 %0, t; }" : "=r"(a) : "l"(p));
    return a;
}
#define SWZ(o) ((o) ^ (((o) >> 3) & 0x70))

__device__ __forceinline__ void ldsm4(u32 addr, u32& r0, u32& r1, u32& r2, u32& r3) {
    asm volatile("ldmatrix.sync.aligned.m8n8.x4.shared.b16 {%0,%1,%2,%3}, [%4];"
                 : "=r"(r0), "=r"(r1), "=r"(r2), "=r"(r3) : "r"(addr));
}
__device__ __forceinline__ void mma16816(float (&d)[4], u32 a0, u32 a1, u32 a2, u32 a3,
                                         u32 b0, u32 b1) {
    asm volatile(
        "mma.sync.aligned.m16n8k16.row.col.f32.bf16.bf16.f32 "
        "{%0,%1,%2,%3},{%4,%5,%6,%7},{%8,%9},{%0,%1,%2,%3};"
        : "+f"(d[0]), "+f"(d[1]), "+f"(d[2]), "+f"(d[3])
        : "r"(a0), "r"(a1), "r"(a2), "r"(a3), "r"(b0), "r"(b1));
}
__device__ __forceinline__ void cpasync16(u32 dst, const void* src) {
    asm volatile("cp.async.cg.shared.global [%0], [%1], 16;" :: "r"(dst), "l"(src));
}
#define CP_COMMIT asm volatile("cp.async.commit_group;" ::: "memory")
#define CP_WAIT(n) asm volatile("cp.async.wait_group %0;" :: "n"(n) : "memory")

__device__ __forceinline__ float silu_f(float x) { return x / (1.0f + __expf(-x)); }
__device__ __forceinline__ void fsplit(float v, bf16& h, bf16& l) {
    h = __float2bfloat16(v);
    l = __float2bfloat16(v - __bfloat162float(h));
}
__device__ __forceinline__ u32 pack2(bf16 a, bf16 b) {
    return (u32)__bfloat16_as_ushort(a) | ((u32)__bfloat16_as_ushort(b) << 16);
}
__device__ __forceinline__ float blo(u32 p) {
    return __bfloat162float(__ushort_as_bfloat16((unsigned short)(p & 0xFFFF)));
}
__device__ __forceinline__ float bhi(u32 p) {
    return __bfloat162float(__ushort_as_bfloat16((unsigned short)(p >> 16)));
}

// ---------------- pre-pass: fp32 -> bf16 hi/lo ----------------
__global__ void split_kernel(const float* __restrict__ s, bf16* __restrict__ h,
                             bf16* __restrict__ l, int n4, float scale) {
    int i = blockIdx.x * blockDim.x + threadIdx.x;
    if (i >= n4) return;
    float4 v = ((const float4*)s)[i];
    v.x *= scale; v.y *= scale; v.z *= scale; v.w *= scale;
    bf16 h0, l0, h1, l1, h2, l2, h3, l3;
    fsplit(v.x, h0, l0); fsplit(v.y, h1, l1); fsplit(v.z, h2, l2); fsplit(v.w, h3, l3);
    uint2 hh, ll;
    hh.x = pack2(h0, h1); hh.y = pack2(h2, h3);
    ll.x = pack2(l0, l1); ll.y = pack2(l2, l3);
    ((uint2*)h)[i] = hh;
    ((uint2*)l)[i] = ll;
}

// v_weight [4096,2048] -> vt [2048,4096], * SCALE, split
__global__ void vtrans_kernel(const float* __restrict__ v, bf16* __restrict__ th,
                              bf16* __restrict__ tl) {
    __shared__ float sm[32][33];
    int c0 = blockIdx.x * 32;
    int m0 = blockIdx.y * 32;
    int tx = threadIdx.x, ty = threadIdx.y;
#pragma unroll
    for (int j = 0; j < 4; j++)
        sm[ty + 8 * j][tx] = v[(size_t)(m0 + ty + 8 * j) * 2048 + c0 + tx] * SCALE_F;
    __syncthreads();
#pragma unroll
    for (int j = 0; j < 4; j++) {
        float x = sm[tx][ty + 8 * j];
        bf16 h, l; fsplit(x, h, l);
        size_t o = (size_t)(c0 + ty + 8 * j) * 4096 + m0 + tx;
        th[o] = h; tl[o] = l;
    }
}

// ---------------- warp-MMA GEMM ----------------
// C[4096x2048] = A[4096x2048] * B[2048x2048]^T (both K-major), split-bf16 3-pass.
// CTA tile 128x128, BK=64, 8 warps (2x4), warp tile 64x32, 2-stage cp.async.
// smem per stage (64KB): Ah 0, Al 16K, Bh 32K, Bl 48K; [128][64] bf16, SW128.
extern __shared__ __align__(16) char smem_dyn[];

template<int SILU, int SPLITOUT>
__global__ __launch_bounds__(256, 1)
void gemm_mma(const bf16* __restrict__ Ah, const bf16* __restrict__ Al,
              const bf16* __restrict__ Bh, const bf16* __restrict__ Bl,
              float* __restrict__ Cf, bf16* __restrict__ Ch, bf16* __restrict__ Cl) {
    const u32 sb = smem_u32(smem_dyn);
    const int tid = threadIdx.x, lane = tid & 31, wid = tid >> 5;
    const int l7 = lane & 7;
    const int m0 = blockIdx.y * 128, n0 = blockIdx.x * 128;
    const int wm = (wid >> 2) * 64, wn = (wid & 3) * 32;

    float acc[4][4][4];
#pragma unroll
    for (int i = 0; i < 4; i++)
#pragma unroll
        for (int j = 0; j < 4; j++)
#pragma unroll
            for (int c = 0; c < 4; c++) acc[i][j][c] = 0.0f;

    auto issue = [&](int it) {
        const int st = it & 1, k0 = it * 64;
        const u32 base = sb + st * 65536;
#pragma unroll
        for (int i = 0; i < 16; i++) {
            int c = tid + i * 256;             // 0..4095
            int t = c >> 10, rem = c & 1023;
            int row = rem >> 3, kc = rem & 7;
            const bf16* gp; int rb;
            if (t == 0)      { gp = Ah; rb = m0; }
            else if (t == 1) { gp = Al; rb = m0; }
            else if (t == 2) { gp = Bh; rb = n0; }
            else             { gp = Bl; rb = n0; }
            const void* src = gp + (size_t)(rb + row) * 2048 + k0 + kc * 8;
            u32 off = (u32)(row * 128 + kc * 16);
            cpasync16(base + t * 16384 + SWZ(off), src);
        }
    };

    issue(0); CP_COMMIT;
    for (int it = 0; it < 32; it++) {
        if (it < 31) { issue(it + 1); CP_COMMIT; CP_WAIT(1); }
        else         { CP_WAIT(0); }
        __syncthreads();
        const u32 base = sb + (it & 1) * 65536;
#pragma unroll
        for (int kk = 0; kk < 4; kk++) {
            // B fragments: 4 n8-frags, hi+lo
            u32 bh[8], bl[8];
#pragma unroll
            for (int g = 0; g < 2; g++) {
                int nrow = wn + g * 16 + l7 + ((lane >> 4) & 1) * 8;
                int kb = kk * 32 + ((lane >> 3) & 1) * 16;
                u32 a = base + 32768 + SWZ((u32)(nrow * 128 + kb));
                ldsm4(a,         bh[4 * g], bh[4 * g + 1], bh[4 * g + 2], bh[4 * g + 3]);
                ldsm4(a + 16384, bl[4 * g], bl[4 * g + 1], bl[4 * g + 2], bl[4 * g + 3]);
            }
#pragma unroll
            for (int mf = 0; mf < 4; mf++) {
                int arow = wm + mf * 16 + l7 + ((lane >> 3) & 1) * 8;
                int akb = kk * 32 + ((lane >> 4) & 1) * 16;
                u32 aaddr = base + SWZ((u32)(arow * 128 + akb));
                u32 a0, a1, a2, a3;
                ldsm4(aaddr, a0, a1, a2, a3);
#pragma unroll
                for (int nf = 0; nf < 4; nf++)
                    mma16816(acc[mf][nf], a0, a1, a2, a3, bh[2 * nf], bh[2 * nf + 1]);
#pragma unroll
                for (int nf = 0; nf < 4; nf++)
                    mma16816(acc[mf][nf], a0, a1, a2, a3, bl[2 * nf], bl[2 * nf + 1]);
                u32 q0, q1, q2, q3;
                ldsm4(aaddr + 16384, q0, q1, q2, q3);
#pragma unroll
                for (int nf = 0; nf < 4; nf++)
                    mma16816(acc[mf][nf], q0, q1, q2, q3, bh[2 * nf], bh[2 * nf + 1]);
            }
        }
        __syncthreads();
    }

    // epilogue: direct register->gmem stores
#pragma unroll
    for (int mf = 0; mf < 4; mf++)
#pragma unroll
        for (int nf = 0; nf < 4; nf++) {
            int row = m0 + wm + mf * 16 + (lane >> 2);
            int col = n0 + wn + nf * 8 + 2 * (lane & 3);
#pragma unroll
            for (int half = 0; half < 2; half++) {
                int r = row + half * 8;
                float v0 = acc[mf][nf][2 * half + 0];
                float v1 = acc[mf][nf][2 * half + 1];
                if (SILU) { v0 = silu_f(v0); v1 = silu_f(v1); }
                size_t o = (size_t)r * 2048 + col;
                if (SPLITOUT) {
                    bf16 h0, lo0, h1, lo1;
                    fsplit(v0, h0, lo0); fsplit(v1, h1, lo1);
                    *(u32*)(Ch + o) = pack2(h0, h1);
                    *(u32*)(Cl + o) = pack2(lo0, lo1);
                } else {
                    float2 w; w.x = v0; w.y = v1;
                    *(float2*)(Cf + o) = w;
                }
            }
        }
}

// ---------------- fused attention (warp-MMA) ----------------
// CTA = (128 q-rows, head, batch). 8 warps, warp = 16 q-rows.
// Q (hi+lo) resident in smem; per 64-key tile: S=Q K^T (3-pass) -> silu/split in
// regs -> O += P V (3-pass). Gate applied in epilogue.
// smem: Q: Qh 0 (2 atoms x16KB), Ql 32K | stage s at 64K+s*64K: Kh 0 (2 atoms x8K),
//       Kl 16K, Vh 32K, Vl 48K.  Total 192KB.
__global__ __launch_bounds__(256, 1)
void attn_mma(const bf16* __restrict__ Qh, const bf16* __restrict__ Ql,
              const bf16* __restrict__ Kh, const bf16* __restrict__ Kl,
              const bf16* __restrict__ Vth, const bf16* __restrict__ Vtl,
              const bf16* __restrict__ Gh, const bf16* __restrict__ Gl,
              bf16* __restrict__ Oh, bf16* __restrict__ Ol) {
    const u32 sb = smem_u32(smem_dyn);
    const int tid = threadIdx.x, lane = tid & 31, wid = tid >> 5;
    const int l7 = lane & 7;
    const int n0 = blockIdx.x * 128;
    const int h  = blockIdx.y;
    const int b  = blockIdx.z;
    const int m0w = wid * 16;
    const size_t qrow0 = (size_t)(b * 2048 + n0);

    // Q preload (plain vector stores)
#pragma unroll
    for (int i = 0; i < 16; i++) {
        int c = tid + i * 256;             // 0..4095
        int t = c >> 11, rem = c & 2047;
        int row = rem >> 4, dc = rem & 15;
        const bf16* src = (t ? Ql : Qh) + (qrow0 + row) * 2048 + h * 128 + dc * 8;
        u32 off = (u32)(t * 32768 + (dc >> 3) * 16384) + SWZ((u32)(row * 128 + (dc & 7) * 16));
        *(uint4*)(smem_dyn + off) = *(const uint4*)src;
    }

    float oacc[16][4];
#pragma unroll
    for (int i = 0; i < 16; i++)
#pragma unroll
        for (int c = 0; c < 4; c++) oacc[i][c] = 0.0f;

    auto issue_kv = [&](int t) {
        const int st = t & 1, m0k = t * 64;
        const u32 base = sb + 65536 + st * 65536;
#pragma unroll
        for (int i = 0; i < 16; i++) {
            int c = tid + i * 256;         // 0..4095
            if (c < 2048) {                // K tiles
                int t2 = c >> 10, rem = c & 1023;
                int key = rem >> 4, dc = rem & 15;
                const void* src = (t2 ? Kl : Kh) + (size_t)(m0k + key) * 2048 + h * 128 + dc * 8;
                u32 dst = base + t2 * 16384 + (dc >> 3) * 8192
                        + SWZ((u32)(key * 128 + (dc & 7) * 16));
                cpasync16(dst, src);
            } else {                       // V tiles
                int c2 = c - 2048;
                int t2 = c2 >> 10, rem = c2 & 1023;
                int dv = rem >> 3, kc = rem & 7;
                const void* src = (t2 ? Vtl : Vth) + (size_t)(h * 128 + dv) * 4096 + m0k + kc * 8;
                u32 dst = base + 32768 + t2 * 16384 + SWZ((u32)(dv * 128 + kc * 16));
                cpasync16(dst, src);
            }
        }
    };

    issue_kv(0); CP_COMMIT;
#pragma unroll 1
    for (int t = 0; t < 64; t++) {
        if (t < 63) { issue_kv(t + 1); CP_COMMIT; CP_WAIT(1); }
        else        { CP_WAIT(0); }
        __syncthreads();
        const u32 kbase = sb + 65536 + (t & 1) * 65536;

        float sacc[8][4];
#pragma unroll
        for (int j = 0; j < 8; j++)
#pragma unroll
            for (int c = 0; c < 4; c++) sacc[j][c] = 0.0f;

#pragma unroll
        for (int kk = 0; kk < 8; kk++) {
            u32 bh[16], bl[16];
#pragma unroll
            for (int g = 0; g < 4; g++) {
                int nrow = g * 16 + l7 + ((lane >> 4) & 1) * 8;
                int d0 = kk * 16 + ((lane >> 3) & 1) * 8;
                u32 a = kbase + (d0 >> 6) * 8192 + SWZ((u32)(nrow * 128 + (d0 & 63) * 2));
                ldsm4(a,         bh[4 * g], bh[4 * g + 1], bh[4 * g + 2], bh[4 * g + 3]);
                ldsm4(a + 16384, bl[4 * g], bl[4 * g + 1], bl[4 * g + 2], bl[4 * g + 3]);
            }
            int arow = m0w + l7 + ((lane >> 3) & 1) * 8;
            int ad0 = kk * 16 + ((lane >> 4) & 1) * 8;
            u32 qa = sb + (ad0 >> 6) * 16384 + SWZ((u32)(arow * 128 + (ad0 & 63) * 2));
            u32 a0, a1, a2, a3;
            ldsm4(qa, a0, a1, a2, a3);
#pragma unroll
            for (int j = 0; j < 8; j++)
                mma16816(sacc[j], a0, a1, a2, a3, bh[2 * j], bh[2 * j + 1]);
#pragma unroll
            for (int j = 0; j < 8; j++)
                mma16816(sacc[j], a0, a1, a2, a3, bl[2 * j], bl[2 * j + 1]);
            u32 q0, q1, q2, q3;
            ldsm4(qa + 32768, q0, q1, q2, q3);
#pragma unroll
            for (int j = 0; j < 8; j++)
                mma16816(sacc[j], q0, q1, q2, q3, bh[2 * j], bh[2 * j + 1]);
        }

        // silu + split (regs) then P @ V
#pragma unroll
        for (int kk2 = 0; kk2 < 4; kk2++) {
            u32 pah[4], pal[4];
#pragma unroll
            for (int q = 0; q < 4; q++) {
                const float* src = sacc[2 * kk2 + (q >> 1)];
                float s0 = silu_f(src[(q & 1) * 2 + 0]);
                float s1 = silu_f(src[(q & 1) * 2 + 1]);
                bf16 h0, lo0, h1, lo1;
                fsplit(s0, h0, lo0); fsplit(s1, h1, lo1);
                pah[q] = pack2(h0, h1);
                pal[q] = pack2(lo0, lo1);
            }
#pragma unroll
            for (int g = 0; g < 8; g++) {
                int nrow = g * 16 + l7 + ((lane >> 4) & 1) * 8;
                int kb = kk2 * 32 + ((lane >> 3) & 1) * 16;
                u32 va = kbase + 32768 + SWZ((u32)(nrow * 128 + kb));
                u32 v0, v1, v2, v3, w0, w1, w2, w3;
                ldsm4(va,         v0, v1, v2, v3);
                ldsm4(va + 16384, w0, w1, w2, w3);
                mma16816(oacc[2 * g],     pah[0], pah[1], pah[2], pah[3], v0, v1);
                mma16816(oacc[2 * g + 1], pah[0], pah[1], pah[2], pah[3], v2, v3);
                mma16816(oacc[2 * g],     pah[0], pah[1], pah[2], pah[3], w0, w1);
                mma16816(oacc[2 * g + 1], pah[0], pah[1], pah[2], pah[3], w2, w3);
                mma16816(oacc[2 * g],     pal[0], pal[1], pal[2], pal[3], v0, v1);
                mma16816(oacc[2 * g + 1], pal[0], pal[1], pal[2], pal[3], v2, v3);
            }
        }
        __syncthreads();
    }

    // epilogue: gate + split-store
#pragma unroll
    for (int nf = 0; nf < 16; nf++) {
        int col = nf * 8 + 2 * (lane & 3);
        int gcol = h * 128 + col;
#pragma unroll
        for (int half = 0; half < 2; half++) {
            int row = m0w + (lane >> 2) + half * 8;
            size_t o = (qrow0 + row) * 2048 + gcol;
            u32 gh2 = *(const u32*)(Gh + o);
            u32 gl2 = *(const u32*)(Gl + o);
            float g0 = blo(gh2) + blo(gl2);
            float g1 = bhi(gh2) + bhi(gl2);
            float v0 = oacc[nf][2 * half + 0] * g0;
            float v1 = oacc[nf][2 * half + 1] * g1;
            bf16 h0, lo0, h1, lo1;
            fsplit(v0, h0, lo0); fsplit(v1, h1, lo1);
            *(u32*)(Oh + o) = pack2(h0, h1);
            *(u32*)(Ol + o) = pack2(lo0, lo1);
        }
    }
}

// ---------------- launch ----------------
#define GETSYM(var, sym) do { void* _p; cudaGetSymbolAddress(&_p, sym); var = (bf16*)_p; } while (0)

extern "C" void kernel_launch(void* const* d_in, const int* in_sizes, int n_in,
                              void* d_out, int out_size) {
    const float* x  = (const float*)d_in[0];
    const float* Wq = (const float*)d_in[1];
    const float* kw = (const float*)d_in[2];
    const float* vw = (const float*)d_in[3];
    const float* Wg = (const float*)d_in[4];
    const float* Wo = (const float*)d_in[5];
    float* out = (float*)d_out;

    bf16 *xh, *xl, *wqh, *wql, *wgh, *wgl, *woh, *wol;
    bf16 *kh, *kl, *vth, *vtl, *qh, *ql, *gh, *gl, *ah, *al;
    GETSYM(xh, g_xh);   GETSYM(xl, g_xl);
    GETSYM(wqh, g_wqh); GETSYM(wql, g_wql);
    GETSYM(wgh, g_wgh); GETSYM(wgl, g_wgl);
    GETSYM(woh, g_woh); GETSYM(wol, g_wol);
    GETSYM(kh, g_kh);   GETSYM(kl, g_kl);
    GETSYM(vth, g_vth); GETSYM(vtl, g_vtl);
    GETSYM(qh, g_qh);   GETSYM(ql, g_ql);
    GETSYM(gh, g_gh);   GETSYM(gl, g_gl);
    GETSYM(ah, g_ah);   GETSYM(al, g_al);

    cudaFuncSetAttribute(gemm_mma<0, 1>, cudaFuncAttributeMaxDynamicSharedMemorySize, 131072);
    cudaFuncSetAttribute(gemm_mma<1, 1>, cudaFuncAttributeMaxDynamicSharedMemorySize, 131072);
    cudaFuncSetAttribute(gemm_mma<0, 0>, cudaFuncAttributeMaxDynamicSharedMemorySize, 131072);
    cudaFuncSetAttribute(attn_mma, cudaFuncAttributeMaxDynamicSharedMemorySize, 196608);

    split_kernel<<<8192, 256>>>(x,  xh,  xl,  2097152, 1.0f);
    split_kernel<<<4096, 256>>>(Wq, wqh, wql, 1048576, 1.0f);
    split_kernel<<<4096, 256>>>(Wg, wgh, wgl, 1048576, 1.0f);
    split_kernel<<<4096, 256>>>(Wo, woh, wol, 1048576, 1.0f);
    split_kernel<<<8192, 256>>>(kw, kh,  kl,  2097152, SCALE_F);
    vtrans_kernel<<<dim3(64, 128), dim3(32, 8)>>>(vw, vth, vtl);

    dim3 gg(16, 32);
    gemm_mma<0, 1><<<gg, 256, 131072>>>(xh, xl, wqh, wql, nullptr, qh, ql);
    gemm_mma<1, 1><<<gg, 256, 131072>>>(xh, xl, wgh, wgl, nullptr, gh, gl);
    attn_mma<<<dim3(16, 16, 2), 256, 196608>>>(qh, ql, kh, kl, vth, vtl, gh, gl, ah, al);
    gemm_mma<0, 0><<<gg, 256, 131072>>>(ah, al, woh, wol, out, nullptr, nullptr);
}

// round 5
// speedup vs baseline: 3.7526x; 1.3385x over previous
#include <cuda_runtime.h>
#include <cuda_fp16.h>

typedef unsigned int u32;
typedef unsigned long long u64;

#define SCALE_F 11.313708498984761f   // sqrt(128)

// ---------------- scratch ----------------
// activations: fp16 hi/lo split; weights: single fp16; gate: fp32
static __device__ __half g_xh[8388608],  g_xl[8388608];
static __device__ __half g_wq[4194304],  g_wg[4194304], g_wo[4194304];
static __device__ __half g_k[8388608];
static __device__ __half g_vt[8388608];
static __device__ __half g_qh[8388608],  g_ql[8388608];
static __device__ float  g_gate[8388608];
static __device__ __half g_ah[8388608],  g_al[8388608];

// ---------------- helpers ----------------
__device__ __forceinline__ u32 smem_u32(const void* p) {
    u32 a;
    asm("{ .reg .u64 t; cvta.to.shared.u64 t, %1; cvt.u32.u64 %0, t; }" : "=r"(a) : "l"(p));
    return a;
}
#define SWZ(o) ((o) ^ (((o) >> 3) & 0x70))

__device__ __forceinline__ void ldsm4(u32 addr, u32& r0, u32& r1, u32& r2, u32& r3) {
    asm volatile("ldmatrix.sync.aligned.m8n8.x4.shared.b16 {%0,%1,%2,%3}, [%4];"
                 : "=r"(r0), "=r"(r1), "=r"(r2), "=r"(r3) : "r"(addr));
}
__device__ __forceinline__ void mma16816(float (&d)[4], u32 a0, u32 a1, u32 a2, u32 a3,
                                         u32 b0, u32 b1) {
    asm volatile(
        "mma.sync.aligned.m16n8k16.row.col.f32.f16.f16.f32 "
        "{%0,%1,%2,%3},{%4,%5,%6,%7},{%8,%9},{%0,%1,%2,%3};"
        : "+f"(d[0]), "+f"(d[1]), "+f"(d[2]), "+f"(d[3])
        : "r"(a0), "r"(a1), "r"(a2), "r"(a3), "r"(b0), "r"(b1));
}
__device__ __forceinline__ void cpasync16(u32 dst, const void* src) {
    asm volatile("cp.async.cg.shared.global [%0], [%1], 16;" :: "r"(dst), "l"(src));
}
#define CP_COMMIT asm volatile("cp.async.commit_group;" ::: "memory")
#define CP_WAIT(n) asm volatile("cp.async.wait_group %0;" :: "n"(n) : "memory")

__device__ __forceinline__ float silu_f(float x) { return x / (1.0f + __expf(-x)); }
__device__ __forceinline__ void fsplit(float v, __half& h, __half& l) {
    h = __float2half_rn(v);
    l = __float2half_rn(v - __half2float(h));
}
__device__ __forceinline__ u32 pack2h(__half a, __half b) {
    return (u32)__half_as_ushort(a) | ((u32)__half_as_ushort(b) << 16);
}

// ---------------- pre-pass kernels ----------------
__global__ void split_kernel(const float* __restrict__ s, __half* __restrict__ h,
                             __half* __restrict__ l, int n4) {
    int i = blockIdx.x * blockDim.x + threadIdx.x;
    if (i >= n4) return;
    float4 v = ((const float4*)s)[i];
    __half h0, l0, h1, l1, h2, l2, h3, l3;
    fsplit(v.x, h0, l0); fsplit(v.y, h1, l1); fsplit(v.z, h2, l2); fsplit(v.w, h3, l3);
    uint2 hh, ll;
    hh.x = pack2h(h0, h1); hh.y = pack2h(h2, h3);
    ll.x = pack2h(l0, l1); ll.y = pack2h(l2, l3);
    ((uint2*)h)[i] = hh;
    ((uint2*)l)[i] = ll;
}

__global__ void conv_kernel(const float* __restrict__ s, __half* __restrict__ d,
                            int n4, float scale) {
    int i = blockIdx.x * blockDim.x + threadIdx.x;
    if (i >= n4) return;
    float4 v = ((const float4*)s)[i];
    uint2 o;
    o.x = pack2h(__float2half_rn(v.x * scale), __float2half_rn(v.y * scale));
    o.y = pack2h(__float2half_rn(v.z * scale), __float2half_rn(v.w * scale));
    ((uint2*)d)[i] = o;
}

// v_weight [4096,2048] -> vt [2048,4096], * SCALE, single fp16
__global__ void vtrans_kernel(const float* __restrict__ v, __half* __restrict__ t) {
    __shared__ float sm[32][33];
    int c0 = blockIdx.x * 32;
    int m0 = blockIdx.y * 32;
    int tx = threadIdx.x, ty = threadIdx.y;
#pragma unroll
    for (int j = 0; j < 4; j++)
        sm[ty + 8 * j][tx] = v[(size_t)(m0 + ty + 8 * j) * 2048 + c0 + tx] * SCALE_F;
    __syncthreads();
#pragma unroll
    for (int j = 0; j < 4; j++) {
        float x = sm[tx][ty + 8 * j];
        t[(size_t)(c0 + ty + 8 * j) * 4096 + m0 + tx] = __float2half_rn(x);
    }
}

// ---------------- warp-MMA GEMM (fp16, 2-pass: A split, B single) ----------------
// C[4096x2048] = (Ah+Al)[4096x2048] * B[2048x2048]^T, both K-major.
// CTA 128x128, BK=64, 8 warps (2x4), warp 64x32, 2-stage cp.async.
// smem/stage 48KB: Ah 0, Al 16K, B 32K; [128][64] fp16 rows (128B), SW128.
extern __shared__ __align__(16) char smem_dyn[];

template<int SILU, int SPLITOUT>
__global__ __launch_bounds__(256, 2)
void gemm_mma(const __half* __restrict__ Ah, const __half* __restrict__ Al,
              const __half* __restrict__ Bw,
              float* __restrict__ Cf, __half* __restrict__ Ch, __half* __restrict__ Cl) {
    const u32 sb = smem_u32(smem_dyn);
    const int tid = threadIdx.x, lane = tid & 31, wid = tid >> 5;
    const int l7 = lane & 7;
    const int m0 = blockIdx.y * 128, n0 = blockIdx.x * 128;
    const int wm = (wid >> 2) * 64, wn = (wid & 3) * 32;

    float acc[4][4][4];
#pragma unroll
    for (int i = 0; i < 4; i++)
#pragma unroll
        for (int j = 0; j < 4; j++)
#pragma unroll
            for (int c = 0; c < 4; c++) acc[i][j][c] = 0.0f;

    auto issue = [&](int it) {
        const int st = it & 1, k0 = it * 64;
        const u32 base = sb + st * 49152;
#pragma unroll
        for (int i = 0; i < 12; i++) {
            int f = tid + i * 256;             // 0..3071
            int t = f >> 10, rem = f & 1023;
            int row = rem >> 3, kc = rem & 7;
            const __half* gp; int rb;
            if (t == 0)      { gp = Ah; rb = m0; }
            else if (t == 1) { gp = Al; rb = m0; }
            else             { gp = Bw; rb = n0; }
            const void* src = gp + (size_t)(rb + row) * 2048 + k0 + kc * 8;
            u32 off = (u32)(row * 128 + kc * 16);
            cpasync16(base + t * 16384 + SWZ(off), src);
        }
    };

    issue(0); CP_COMMIT;
    for (int it = 0; it < 32; it++) {
        if (it < 31) { issue(it + 1); CP_COMMIT; CP_WAIT(1); }
        else         { CP_WAIT(0); }
        __syncthreads();
        const u32 base = sb + (it & 1) * 49152;
#pragma unroll
        for (int kk = 0; kk < 4; kk++) {
            u32 bh[8];
#pragma unroll
            for (int g = 0; g < 2; g++) {
                int nrow = wn + g * 16 + l7 + ((lane >> 4) & 1) * 8;
                int kb = kk * 32 + ((lane >> 3) & 1) * 16;
                u32 a = base + 32768 + SWZ((u32)(nrow * 128 + kb));
                ldsm4(a, bh[4 * g], bh[4 * g + 1], bh[4 * g + 2], bh[4 * g + 3]);
            }
#pragma unroll
            for (int mf = 0; mf < 4; mf++) {
                int arow = wm + mf * 16 + l7 + ((lane >> 3) & 1) * 8;
                int akb = kk * 32 + ((lane >> 4) & 1) * 16;
                u32 aaddr = base + SWZ((u32)(arow * 128 + akb));
                u32 a0, a1, a2, a3;
                ldsm4(aaddr, a0, a1, a2, a3);
#pragma unroll
                for (int nf = 0; nf < 4; nf++)
                    mma16816(acc[mf][nf], a0, a1, a2, a3, bh[2 * nf], bh[2 * nf + 1]);
                u32 q0, q1, q2, q3;
                ldsm4(aaddr + 16384, q0, q1, q2, q3);
#pragma unroll
                for (int nf = 0; nf < 4; nf++)
                    mma16816(acc[mf][nf], q0, q1, q2, q3, bh[2 * nf], bh[2 * nf + 1]);
            }
        }
        __syncthreads();
    }

#pragma unroll
    for (int mf = 0; mf < 4; mf++)
#pragma unroll
        for (int nf = 0; nf < 4; nf++) {
            int row = m0 + wm + mf * 16 + (lane >> 2);
            int col = n0 + wn + nf * 8 + 2 * (lane & 3);
#pragma unroll
            for (int half = 0; half < 2; half++) {
                int r = row + half * 8;
                float v0 = acc[mf][nf][2 * half + 0];
                float v1 = acc[mf][nf][2 * half + 1];
                if (SILU) { v0 = silu_f(v0); v1 = silu_f(v1); }
                size_t o = (size_t)r * 2048 + col;
                if (SPLITOUT) {
                    __half h0, lo0, h1, lo1;
                    fsplit(v0, h0, lo0); fsplit(v1, h1, lo1);
                    *(u32*)(Ch + o) = pack2h(h0, h1);
                    *(u32*)(Cl + o) = pack2h(lo0, lo1);
                } else {
                    float2 w; w.x = v0; w.y = v1;
                    *(float2*)(Cf + o) = w;
                }
            }
        }
}

// ---------------- fused attention (fp16, 2-pass) ----------------
// CTA = (128 q-rows, head, batch), 8 warps x 16 rows.
// S = (Qh+Ql) K^T (K single); P=silu(S) split in regs; O += (Ph+Pl) V (V single).
// smem: Qh 0 (2x16K halves), Ql 32K | stage s at 64K+s*32K: K 16K, V 16K. total 128K.
__global__ __launch_bounds__(256, 1)
void attn_mma(const __half* __restrict__ Qh, const __half* __restrict__ Ql,
              const __half* __restrict__ Kw, const __half* __restrict__ Vt,
              const float* __restrict__ Gate,
              __half* __restrict__ Oh, __half* __restrict__ Ol) {
    const u32 sb = smem_u32(smem_dyn);
    const int tid = threadIdx.x, lane = tid & 31, wid = tid >> 5;
    const int l7 = lane & 7;
    const int n0 = blockIdx.x * 128;
    const int h  = blockIdx.y;
    const int b  = blockIdx.z;
    const int m0w = wid * 16;
    const size_t qrow0 = (size_t)(b * 2048 + n0);

    // Q preload (hi+lo)
#pragma unroll
    for (int i = 0; i < 16; i++) {
        int f = tid + i * 256;             // 0..4095
        int t = f >> 11, rem = f & 2047;
        int row = rem >> 4, dc = rem & 15;
        const __half* src = (t ? Ql : Qh) + (qrow0 + row) * 2048 + h * 128 + dc * 8;
        u32 off = (u32)(t * 32768 + (dc >> 3) * 16384) + SWZ((u32)(row * 128 + (dc & 7) * 16));
        *(uint4*)(smem_dyn + off) = *(const uint4*)src;
    }

    float oacc[16][4];
#pragma unroll
    for (int i = 0; i < 16; i++)
#pragma unroll
        for (int c = 0; c < 4; c++) oacc[i][c] = 0.0f;

    auto issue_kv = [&](int t) {
        const int st = t & 1, m0k = t * 64;
        const u32 base = sb + 65536 + st * 32768;
#pragma unroll
        for (int i = 0; i < 8; i++) {
            int f = tid + i * 256;         // 0..2047
            if (f < 1024) {                // K tile: 64 keys x 128 dk
                int key = f >> 4, dc = f & 15;
                const void* src = Kw + (size_t)(m0k + key) * 2048 + h * 128 + dc * 8;
                u32 dst = base + (dc >> 3) * 8192 + SWZ((u32)(key * 128 + (dc & 7) * 16));
                cpasync16(dst, src);
            } else {                       // V tile: 128 dv x 64 keys
                int f2 = f - 1024;
                int dv = f2 >> 3, kc = f2 & 7;
                const void* src = Vt + (size_t)(h * 128 + dv) * 4096 + m0k + kc * 8;
                u32 dst = base + 16384 + SWZ((u32)(dv * 128 + kc * 16));
                cpasync16(dst, src);
            }
        }
    };

    issue_kv(0); CP_COMMIT;
#pragma unroll 1
    for (int t = 0; t < 64; t++) {
        if (t < 63) { issue_kv(t + 1); CP_COMMIT; CP_WAIT(1); }
        else        { CP_WAIT(0); }
        __syncthreads();
        const u32 kbase = sb + 65536 + (t & 1) * 32768;

        float sacc[8][4];
#pragma unroll
        for (int j = 0; j < 8; j++)
#pragma unroll
            for (int c = 0; c < 4; c++) sacc[j][c] = 0.0f;

#pragma unroll
        for (int kk = 0; kk < 8; kk++) {
            u32 bh[16];
#pragma unroll
            for (int g = 0; g < 4; g++) {
                int nrow = g * 16 + l7 + ((lane >> 4) & 1) * 8;
                int d0 = kk * 16 + ((lane >> 3) & 1) * 8;
                u32 a = kbase + (d0 >> 6) * 8192 + SWZ((u32)(nrow * 128 + (d0 & 63) * 2));
                ldsm4(a, bh[4 * g], bh[4 * g + 1], bh[4 * g + 2], bh[4 * g + 3]);
            }
            int arow = m0w + l7 + ((lane >> 3) & 1) * 8;
            int ad0 = kk * 16 + ((lane >> 4) & 1) * 8;
            u32 qa = sb + (ad0 >> 6) * 16384 + SWZ((u32)(arow * 128 + (ad0 & 63) * 2));
            u32 a0, a1, a2, a3;
            ldsm4(qa, a0, a1, a2, a3);
#pragma unroll
            for (int j = 0; j < 8; j++)
                mma16816(sacc[j], a0, a1, a2, a3, bh[2 * j], bh[2 * j + 1]);
            u32 q0, q1, q2, q3;
            ldsm4(qa + 32768, q0, q1, q2, q3);
#pragma unroll
            for (int j = 0; j < 8; j++)
                mma16816(sacc[j], q0, q1, q2, q3, bh[2 * j], bh[2 * j + 1]);
        }

        // silu + split (regs) then P @ V (2-pass)
#pragma unroll
        for (int kk2 = 0; kk2 < 4; kk2++) {
            u32 pah[4], pal[4];
#pragma unroll
            for (int q = 0; q < 4; q++) {
                const float* src = sacc[2 * kk2 + (q >> 1)];
                float s0 = silu_f(src[(q & 1) * 2 + 0]);
                float s1 = silu_f(src[(q & 1) * 2 + 1]);
                __half h0, lo0, h1, lo1;
                fsplit(s0, h0, lo0); fsplit(s1, h1, lo1);
                pah[q] = pack2h(h0, h1);
                pal[q] = pack2h(lo0, lo1);
            }
#pragma unroll
            for (int g = 0; g < 8; g++) {
                int nrow = g * 16 + l7 + ((lane >> 4) & 1) * 8;
                int kb = kk2 * 32 + ((lane >> 3) & 1) * 16;
                u32 va = kbase + 16384 + SWZ((u32)(nrow * 128 + kb));
                u32 v0, v1, v2, v3;
                ldsm4(va, v0, v1, v2, v3);
                mma16816(oacc[2 * g],     pah[0], pah[1], pah[2], pah[3], v0, v1);
                mma16816(oacc[2 * g + 1], pah[0], pah[1], pah[2], pah[3], v2, v3);
                mma16816(oacc[2 * g],     pal[0], pal[1], pal[2], pal[3], v0, v1);
                mma16816(oacc[2 * g + 1], pal[0], pal[1], pal[2], pal[3], v2, v3);
            }
        }
        __syncthreads();
    }

    // epilogue: gate (fp32) + split-store
#pragma unroll
    for (int nf = 0; nf < 16; nf++) {
        int col = nf * 8 + 2 * (lane & 3);
        int gcol = h * 128 + col;
#pragma unroll
        for (int half = 0; half < 2; half++) {
            int row = m0w + (lane >> 2) + half * 8;
            size_t o = (qrow0 + row) * 2048 + gcol;
            float2 g = *(const float2*)(Gate + o);
            float v0 = oacc[nf][2 * half + 0] * g.x;
            float v1 = oacc[nf][2 * half + 1] * g.y;
            __half h0, lo0, h1, lo1;
            fsplit(v0, h0, lo0); fsplit(v1, h1, lo1);
            *(u32*)(Oh + o) = pack2h(h0, h1);
            *(u32*)(Ol + o) = pack2h(lo0, lo1);
        }
    }
}

// ---------------- launch ----------------
#define GETSYMH(var, sym) do { void* _p; cudaGetSymbolAddress(&_p, sym); var = (__half*)_p; } while (0)

extern "C" void kernel_launch(void* const* d_in, const int* in_sizes, int n_in,
                              void* d_out, int out_size) {
    const float* x  = (const float*)d_in[0];
    const float* Wq = (const float*)d_in[1];
    const float* kw = (const float*)d_in[2];
    const float* vw = (const float*)d_in[3];
    const float* Wg = (const float*)d_in[4];
    const float* Wo = (const float*)d_in[5];
    float* out = (float*)d_out;

    __half *xh, *xl, *wq, *wg, *wo, *k, *vt, *qh, *ql, *ah, *al;
    float* gate;
    GETSYMH(xh, g_xh);  GETSYMH(xl, g_xl);
    GETSYMH(wq, g_wq);  GETSYMH(wg, g_wg);  GETSYMH(wo, g_wo);
    GETSYMH(k,  g_k);   GETSYMH(vt, g_vt);
    GETSYMH(qh, g_qh);  GETSYMH(ql, g_ql);
    GETSYMH(ah, g_ah);  GETSYMH(al, g_al);
    { void* _p; cudaGetSymbolAddress(&_p, g_gate); gate = (float*)_p; }

    cudaFuncSetAttribute(gemm_mma<0, 1>, cudaFuncAttributeMaxDynamicSharedMemorySize, 98304);
    cudaFuncSetAttribute(gemm_mma<1, 0>, cudaFuncAttributeMaxDynamicSharedMemorySize, 98304);
    cudaFuncSetAttribute(gemm_mma<0, 0>, cudaFuncAttributeMaxDynamicSharedMemorySize, 98304);
    cudaFuncSetAttribute(attn_mma, cudaFuncAttributeMaxDynamicSharedMemorySize, 131072);

    // x: 8388608 elems -> n4=2097152 -> 8192 blocks of 256
    split_kernel<<<8192, 256>>>(x, xh, xl, 2097152);
    // weights: 4194304 elems -> n4=1048576 -> 4096 blocks
    conv_kernel<<<4096, 256>>>(Wq, wq, 1048576, 1.0f);
    conv_kernel<<<4096, 256>>>(Wg, wg, 1048576, 1.0f);
    conv_kernel<<<4096, 256>>>(Wo, wo, 1048576, 1.0f);
    // k_weight: 8388608 elems -> n4=2097152 -> 8192 blocks
    conv_kernel<<<8192, 256>>>(kw, k, 2097152, SCALE_F);
    vtrans_kernel<<<dim3(64, 128), dim3(32, 8)>>>(vw, vt);

    dim3 gg(16, 32);
    gemm_mma<0, 1><<<gg, 256, 98304>>>(xh, xl, wq, nullptr, qh, ql);           // q (split out)
    gemm_mma<1, 0><<<gg, 256, 98304>>>(xh, xl, wg, gate, nullptr, nullptr);    // gate = silu(.), fp32
    attn_mma<<<dim3(16, 16, 2), 256, 131072>>>(qh, ql, k, vt, gate, ah, al);
    gemm_mma<0, 0><<<gg, 256, 98304>>>(ah, al, wo, out, nullptr, nullptr);     // final, fp32 out
}

// round 6
// speedup vs baseline: 6.6240x; 1.7652x over previous
#include <cuda_runtime.h>
#include <cuda_fp16.h>

typedef unsigned int u32;

#define SCALE_F 11.313708498984761f   // sqrt(128)

// ---------------- scratch (all single fp16; gate fp32) ----------------
static __device__ __half g_x[8388608];
static __device__ __half g_wq[4194304], g_wg[4194304], g_wo[4194304];
static __device__ __half g_k[8388608];
static __device__ __half g_vt[8388608];
static __device__ __half g_q[8388608];
static __device__ float  g_gate[8388608];
static __device__ __half g_a[8388608];

// ---------------- helpers ----------------
__device__ __forceinline__ u32 smem_u32(const void* p) {
    u32 a;
    asm("{ .reg .u64 t; cvta.to.shared.u64 t, %1; cvt.u32.u64 %0, t; }" : "=r"(a) : "l"(p));
    return a;
}
#define SWZ(o) ((o) ^ (((o) >> 3) & 0x70))

__device__ __forceinline__ void ldsm4(u32 addr, u32& r0, u32& r1, u32& r2, u32& r3) {
    asm volatile("ldmatrix.sync.aligned.m8n8.x4.shared.b16 {%0,%1,%2,%3}, [%4];"
                 : "=r"(r0), "=r"(r1), "=r"(r2), "=r"(r3) : "r"(addr));
}
__device__ __forceinline__ void mma16816(float (&d)[4], u32 a0, u32 a1, u32 a2, u32 a3,
                                         u32 b0, u32 b1) {
    asm volatile(
        "mma.sync.aligned.m16n8k16.row.col.f32.f16.f16.f32 "
        "{%0,%1,%2,%3},{%4,%5,%6,%7},{%8,%9},{%0,%1,%2,%3};"
        : "+f"(d[0]), "+f"(d[1]), "+f"(d[2]), "+f"(d[3])
        : "r"(a0), "r"(a1), "r"(a2), "r"(a3), "r"(b0), "r"(b1));
}
__device__ __forceinline__ void cpasync16(u32 dst, const void* src) {
    asm volatile("cp.async.cg.shared.global [%0], [%1], 16;" :: "r"(dst), "l"(src));
}
#define CP_COMMIT asm volatile("cp.async.commit_group;" ::: "memory")
#define CP_WAIT(n) asm volatile("cp.async.wait_group %0;" :: "n"(n) : "memory")

__device__ __forceinline__ float silu_f(float x) { return x / (1.0f + __expf(-x)); }
__device__ __forceinline__ u32 pack2h(__half a, __half b) {
    return (u32)__half_as_ushort(a) | ((u32)__half_as_ushort(b) << 16);
}

// ---------------- pre-pass ----------------
__global__ void conv_kernel(const float* __restrict__ s, __half* __restrict__ d,
                            int n4, float scale) {
    int i = blockIdx.x * blockDim.x + threadIdx.x;
    if (i >= n4) return;
    float4 v = ((const float4*)s)[i];
    uint2 o;
    o.x = pack2h(__float2half_rn(v.x * scale), __float2half_rn(v.y * scale));
    o.y = pack2h(__float2half_rn(v.z * scale), __float2half_rn(v.w * scale));
    ((uint2*)d)[i] = o;
}

// v_weight [4096,2048] -> vt [2048,4096], * SCALE
__global__ void vtrans_kernel(const float* __restrict__ v, __half* __restrict__ t) {
    __shared__ float sm[32][33];
    int c0 = blockIdx.x * 32;
    int m0 = blockIdx.y * 32;
    int tx = threadIdx.x, ty = threadIdx.y;
#pragma unroll
    for (int j = 0; j < 4; j++)
        sm[ty + 8 * j][tx] = v[(size_t)(m0 + ty + 8 * j) * 2048 + c0 + tx] * SCALE_F;
    __syncthreads();
#pragma unroll
    for (int j = 0; j < 4; j++)
        t[(size_t)(c0 + ty + 8 * j) * 4096 + m0 + tx] = __float2half_rn(sm[tx][ty + 8 * j]);
}

// ---------------- warp-MMA GEMM (fp16 single-pass) ----------------
// C[4096x2048] = A[4096x2048] * B[2048x2048]^T, both K-major.
// CTA 128x128, BK=64, 8 warps (2x4), warp 64x32, 3-stage cp.async, 2 CTA/SM.
// smem/stage 32KB: A 16K, B 16K; [128][64] fp16 rows (128B), SW128.
extern __shared__ __align__(16) char smem_dyn[];

template<int SILU, int HALFOUT>
__global__ __launch_bounds__(256, 2)
void gemm_mma(const __half* __restrict__ A, const __half* __restrict__ Bw,
              float* __restrict__ Cf, __half* __restrict__ Ch) {
    const u32 sb = smem_u32(smem_dyn);
    const int tid = threadIdx.x, lane = tid & 31, wid = tid >> 5;
    const int l7 = lane & 7;
    const int m0 = blockIdx.y * 128, n0 = blockIdx.x * 128;
    const int wm = (wid >> 2) * 64, wn = (wid & 3) * 32;

    float acc[4][4][4];
#pragma unroll
    for (int i = 0; i < 4; i++)
#pragma unroll
        for (int j = 0; j < 4; j++)
#pragma unroll
            for (int c = 0; c < 4; c++) acc[i][j][c] = 0.0f;

    auto issue = [&](int it) {
        const int k0 = it * 64;
        const u32 base = sb + (it % 3) * 32768;
#pragma unroll
        for (int i = 0; i < 8; i++) {
            int f = tid + i * 256;             // 0..2047
            int t = f >> 10, rem = f & 1023;
            int row = rem >> 3, kc = rem & 7;
            const __half* gp = t ? Bw : A;
            int rb = t ? n0 : m0;
            const void* src = gp + (size_t)(rb + row) * 2048 + k0 + kc * 8;
            cpasync16(base + t * 16384 + SWZ((u32)(row * 128 + kc * 16)), src);
        }
    };

    issue(0); CP_COMMIT;
    issue(1); CP_COMMIT;
    for (int it = 0; it < 32; it++) {
        if (it < 30) { CP_WAIT(1); } else { CP_WAIT(0); }
        __syncthreads();
        if (it + 2 < 32) { issue(it + 2); CP_COMMIT; }
        const u32 base = sb + (it % 3) * 32768;
#pragma unroll
        for (int kk = 0; kk < 4; kk++) {
            u32 bh[8];
#pragma unroll
            for (int g = 0; g < 2; g++) {
                int nrow = wn + g * 16 + l7 + ((lane >> 4) & 1) * 8;
                int kb = kk * 32 + ((lane >> 3) & 1) * 16;
                u32 a = base + 16384 + SWZ((u32)(nrow * 128 + kb));
                ldsm4(a, bh[4 * g], bh[4 * g + 1], bh[4 * g + 2], bh[4 * g + 3]);
            }
#pragma unroll
            for (int mf = 0; mf < 4; mf++) {
                int arow = wm + mf * 16 + l7 + ((lane >> 3) & 1) * 8;
                int akb = kk * 32 + ((lane >> 4) & 1) * 16;
                u32 a0, a1, a2, a3;
                ldsm4(base + SWZ((u32)(arow * 128 + akb)), a0, a1, a2, a3);
#pragma unroll
                for (int nf = 0; nf < 4; nf++)
                    mma16816(acc[mf][nf], a0, a1, a2, a3, bh[2 * nf], bh[2 * nf + 1]);
            }
        }
        __syncthreads();
    }

#pragma unroll
    for (int mf = 0; mf < 4; mf++)
#pragma unroll
        for (int nf = 0; nf < 4; nf++) {
            int row = m0 + wm + mf * 16 + (lane >> 2);
            int col = n0 + wn + nf * 8 + 2 * (lane & 3);
#pragma unroll
            for (int half = 0; half < 2; half++) {
                int r = row + half * 8;
                float v0 = acc[mf][nf][2 * half + 0];
                float v1 = acc[mf][nf][2 * half + 1];
                if (SILU) { v0 = silu_f(v0); v1 = silu_f(v1); }
                size_t o = (size_t)r * 2048 + col;
                if (HALFOUT) {
                    *(u32*)(Ch + o) = pack2h(__float2half_rn(v0), __float2half_rn(v1));
                } else {
                    float2 w; w.x = v0; w.y = v1;
                    *(float2*)(Cf + o) = w;
                }
            }
        }
}

// ---------------- fused attention (fp16 single-pass) ----------------
// CTA = (128 q-rows, head, batch), 8 warps x 16 rows, 2 CTA/SM.
// S = Q K^T; P = silu(S) (fp16); O += P V. Gate (fp32) in epilogue.
// smem: Q 32K (two 16K d-halves) | stage s at 32K + s*32K: K 16K (two 8K d-halves), V 16K.
// Total 96K. S processed in two 32-key halves to cap registers.
__global__ __launch_bounds__(256, 2)
void attn_mma(const __half* __restrict__ Q, const __half* __restrict__ Kw,
              const __half* __restrict__ Vt, const float* __restrict__ Gate,
              __half* __restrict__ O) {
    const u32 sb = smem_u32(smem_dyn);
    const int tid = threadIdx.x, lane = tid & 31, wid = tid >> 5;
    const int l7 = lane & 7;
    const int n0 = blockIdx.x * 128;
    const int h  = blockIdx.y;
    const int b  = blockIdx.z;
    const int m0w = wid * 16;
    const size_t qrow0 = (size_t)(b * 2048 + n0);

    // Q preload: 128 rows x 128 d fp16 = 32KB
#pragma unroll
    for (int i = 0; i < 8; i++) {
        int f = tid + i * 256;             // 0..2047
        int row = f >> 4, dc = f & 15;
        const __half* src = Q + (qrow0 + row) * 2048 + h * 128 + dc * 8;
        u32 off = (u32)((dc >> 3) * 16384) + SWZ((u32)(row * 128 + (dc & 7) * 16));
        *(uint4*)(smem_dyn + off) = *(const uint4*)src;
    }

    float oacc[16][4];
#pragma unroll
    for (int i = 0; i < 16; i++)
#pragma unroll
        for (int c = 0; c < 4; c++) oacc[i][c] = 0.0f;

    auto issue_kv = [&](int t) {
        const int m0k = t * 64;
        const u32 base = sb + 32768 + (t & 1) * 32768;
#pragma unroll
        for (int i = 0; i < 8; i++) {
            int f = tid + i * 256;         // 0..2047
            if (f < 1024) {                // K tile: 64 keys x 128 d
                int key = f >> 4, dc = f & 15;
                const void* src = Kw + (size_t)(m0k + key) * 2048 + h * 128 + dc * 8;
                u32 dst = base + (dc >> 3) * 8192 + SWZ((u32)(key * 128 + (dc & 7) * 16));
                cpasync16(dst, src);
            } else {                       // V tile: 128 dv x 64 keys
                int f2 = f - 1024;
                int dv = f2 >> 3, kc = f2 & 7;
                const void* src = Vt + (size_t)(h * 128 + dv) * 4096 + m0k + kc * 8;
                cpasync16(base + 16384 + SWZ((u32)(dv * 128 + kc * 16)), src);
            }
        }
    };

    issue_kv(0); CP_COMMIT;
#pragma unroll 1
    for (int t = 0; t < 64; t++) {
        if (t < 63) { issue_kv(t + 1); CP_COMMIT; CP_WAIT(1); }
        else        { CP_WAIT(0); }
        __syncthreads();
        const u32 kbase = sb + 32768 + (t & 1) * 32768;

#pragma unroll
        for (int half = 0; half < 2; half++) {     // keys [32*half, 32*half+32)
            float sacc[4][4];
#pragma unroll
            for (int j = 0; j < 4; j++)
#pragma unroll
                for (int c = 0; c < 4; c++) sacc[j][c] = 0.0f;

#pragma unroll
            for (int kk = 0; kk < 8; kk++) {       // d chunks of 16
                u32 bh[8];
#pragma unroll
                for (int g = 0; g < 2; g++) {
                    int nrow = half * 32 + g * 16 + l7 + ((lane >> 4) & 1) * 8;
                    int d0 = kk * 16 + ((lane >> 3) & 1) * 8;
                    u32 a = kbase + (d0 >> 6) * 8192 + SWZ((u32)(nrow * 128 + (d0 & 63) * 2));
                    ldsm4(a, bh[4 * g], bh[4 * g + 1], bh[4 * g + 2], bh[4 * g + 3]);
                }
                int arow = m0w + l7 + ((lane >> 3) & 1) * 8;
                int ad0 = kk * 16 + ((lane >> 4) & 1) * 8;
                u32 qa = sb + (ad0 >> 6) * 16384 + SWZ((u32)(arow * 128 + (ad0 & 63) * 2));
                u32 a0, a1, a2, a3;
                ldsm4(qa, a0, a1, a2, a3);
#pragma unroll
                for (int j = 0; j < 4; j++)
                    mma16816(sacc[j], a0, a1, a2, a3, bh[2 * j], bh[2 * j + 1]);
            }

            // silu -> fp16 P (regs), then P @ V for this half's 2 key-chunks
#pragma unroll
            for (int kk2l = 0; kk2l < 2; kk2l++) {
                int kk2 = half * 2 + kk2l;
                u32 pa[4];
#pragma unroll
                for (int q = 0; q < 4; q++) {
                    const float* src = sacc[2 * kk2l + (q >> 1)];
                    float s0 = silu_f(src[(q & 1) * 2 + 0]);
                    float s1 = silu_f(src[(q & 1) * 2 + 1]);
                    pa[q] = pack2h(__float2half_rn(s0), __float2half_rn(s1));
                }
#pragma unroll
                for (int g = 0; g < 8; g++) {
                    int nrow = g * 16 + l7 + ((lane >> 4) & 1) * 8;
                    int kb = kk2 * 32 + ((lane >> 3) & 1) * 16;
                    u32 va = kbase + 16384 + SWZ((u32)(nrow * 128 + kb));
                    u32 v0, v1, v2, v3;
                    ldsm4(va, v0, v1, v2, v3);
                    mma16816(oacc[2 * g],     pa[0], pa[1], pa[2], pa[3], v0, v1);
                    mma16816(oacc[2 * g + 1], pa[0], pa[1], pa[2], pa[3], v2, v3);
                }
            }
        }
        __syncthreads();
    }

    // epilogue: gate (fp32) + fp16 store
#pragma unroll
    for (int nf = 0; nf < 16; nf++) {
        int col = nf * 8 + 2 * (lane & 3);
        int gcol = h * 128 + col;
#pragma unroll
        for (int half = 0; half < 2; half++) {
            int row = m0w + (lane >> 2) + half * 8;
            size_t o = (qrow0 + row) * 2048 + gcol;
            float2 g = *(const float2*)(Gate + o);
            float v0 = oacc[nf][2 * half + 0] * g.x;
            float v1 = oacc[nf][2 * half + 1] * g.y;
            *(u32*)(O + o) = pack2h(__float2half_rn(v0), __float2half_rn(v1));
        }
    }
}

// ---------------- launch ----------------
#define GETSYMH(var, sym) do { void* _p; cudaGetSymbolAddress(&_p, sym); var = (__half*)_p; } while (0)

extern "C" void kernel_launch(void* const* d_in, const int* in_sizes, int n_in,
                              void* d_out, int out_size) {
    const float* x  = (const float*)d_in[0];
    const float* Wq = (const float*)d_in[1];
    const float* kw = (const float*)d_in[2];
    const float* vw = (const float*)d_in[3];
    const float* Wg = (const float*)d_in[4];
    const float* Wo = (const float*)d_in[5];
    float* out = (float*)d_out;

    __half *xh, *wq, *wg, *wo, *k, *vt, *qp, *ap;
    float* gate;
    GETSYMH(xh, g_x);
    GETSYMH(wq, g_wq); GETSYMH(wg, g_wg); GETSYMH(wo, g_wo);
    GETSYMH(k,  g_k);  GETSYMH(vt, g_vt);
    GETSYMH(qp, g_q);  GETSYMH(ap, g_a);
    { void* _p; cudaGetSymbolAddress(&_p, g_gate); gate = (float*)_p; }

    cudaFuncSetAttribute(gemm_mma<0, 1>, cudaFuncAttributeMaxDynamicSharedMemorySize, 98304);
    cudaFuncSetAttribute(gemm_mma<1, 0>, cudaFuncAttributeMaxDynamicSharedMemorySize, 98304);
    cudaFuncSetAttribute(gemm_mma<0, 0>, cudaFuncAttributeMaxDynamicSharedMemorySize, 98304);
    cudaFuncSetAttribute(attn_mma, cudaFuncAttributeMaxDynamicSharedMemorySize, 98304);

    conv_kernel<<<8192, 256>>>(x,  xh, 2097152, 1.0f);
    conv_kernel<<<4096, 256>>>(Wq, wq, 1048576, 1.0f);
    conv_kernel<<<4096, 256>>>(Wg, wg, 1048576, 1.0f);
    conv_kernel<<<4096, 256>>>(Wo, wo, 1048576, 1.0f);
    conv_kernel<<<8192, 256>>>(kw, k,  2097152, SCALE_F);
    vtrans_kernel<<<dim3(64, 128), dim3(32, 8)>>>(vw, vt);

    dim3 gg(16, 32);
    gemm_mma<0, 1><<<gg, 256, 98304>>>(xh, wq, nullptr, qp);        // q (fp16)
    gemm_mma<1, 0><<<gg, 256, 98304>>>(xh, wg, gate, nullptr);      // gate = silu(.), fp32
    attn_mma<<<dim3(16, 16, 2), 256, 98304>>>(qp, k, vt, gate, ap); // attn * gate (fp16)
    gemm_mma<0, 0><<<gg, 256, 98304>>>(ap, wo, out, nullptr);       // final, fp32 out
}

// round 7
// speedup vs baseline: 6.6574x; 1.0051x over previous
#include <cuda_runtime.h>
#include <cuda_fp16.h>

typedef unsigned int u32;

#define SCALE_F 11.313708498984761f   // sqrt(128)

// ---------------- scratch (all single fp16; gate fp32) ----------------
static __device__ __half g_x[8388608];
static __device__ __half g_wq[4194304], g_wg[4194304], g_wo[4194304];
static __device__ __half g_k[8388608];
static __device__ __half g_vt[8388608];
static __device__ __half g_q[8388608];
static __device__ float  g_gate[8388608];
static __device__ __half g_a[8388608];

// ---------------- helpers ----------------
__device__ __forceinline__ u32 smem_u32(const void* p) {
    u32 a;
    asm("{ .reg .u64 t; cvta.to.shared.u64 t, %1; cvt.u32.u64 %0, t; }" : "=r"(a) : "l"(p));
    return a;
}
#define SWZ(o) ((o) ^ (((o) >> 3) & 0x70))

__device__ __forceinline__ void ldsm4(u32 addr, u32& r0, u32& r1, u32& r2, u32& r3) {
    asm volatile("ldmatrix.sync.aligned.m8n8.x4.shared.b16 {%0,%1,%2,%3}, [%4];"
                 : "=r"(r0), "=r"(r1), "=r"(r2), "=r"(r3) : "r"(addr));
}
__device__ __forceinline__ void mma16816(float (&d)[4], u32 a0, u32 a1, u32 a2, u32 a3,
                                         u32 b0, u32 b1) {
    asm volatile(
        "mma.sync.aligned.m16n8k16.row.col.f32.f16.f16.f32 "
        "{%0,%1,%2,%3},{%4,%5,%6,%7},{%8,%9},{%0,%1,%2,%3};"
        : "+f"(d[0]), "+f"(d[1]), "+f"(d[2]), "+f"(d[3])
        : "r"(a0), "r"(a1), "r"(a2), "r"(a3), "r"(b0), "r"(b1));
}
__device__ __forceinline__ void cpasync16(u32 dst, const void* src) {
    asm volatile("cp.async.cg.shared.global [%0], [%1], 16;" :: "r"(dst), "l"(src));
}
#define CP_COMMIT asm volatile("cp.async.commit_group;" ::: "memory")
#define CP_WAIT(n) asm volatile("cp.async.wait_group %0;" :: "n"(n) : "memory")

__device__ __forceinline__ float silu_f(float x) { return x / (1.0f + __expf(-x)); }
__device__ __forceinline__ u32 pack2h(__half a, __half b) {
    return (u32)__half_as_ushort(a) | ((u32)__half_as_ushort(b) << 16);
}

// ---------------- pre-pass (merged) ----------------
// grid.y selects tensor; fp32 -> fp16 (optional scale).
__global__ void conv_act_kernel(const float* __restrict__ x, __half* __restrict__ dx,
                                const float* __restrict__ kw, __half* __restrict__ dk) {
    int i = blockIdx.x * blockDim.x + threadIdx.x;   // 0..2097151 (n4)
    if (i >= 2097152) return;
    const float* s;
    __half* d;
    float scale;
    if (blockIdx.y == 0) { s = x;  d = dx; scale = 1.0f; }
    else                 { s = kw; d = dk; scale = SCALE_F; }
    float4 v = ((const float4*)s)[i];
    uint2 o;
    o.x = pack2h(__float2half_rn(v.x * scale), __float2half_rn(v.y * scale));
    o.y = pack2h(__float2half_rn(v.z * scale), __float2half_rn(v.w * scale));
    ((uint2*)d)[i] = o;
}

__global__ void conv_w_kernel(const float* __restrict__ wq, __half* __restrict__ dq,
                              const float* __restrict__ wg, __half* __restrict__ dg,
                              const float* __restrict__ wo, __half* __restrict__ dw) {
    int i = blockIdx.x * blockDim.x + threadIdx.x;   // 0..1048575 (n4)
    if (i >= 1048576) return;
    const float* s;
    __half* d;
    if (blockIdx.y == 0)      { s = wq; d = dq; }
    else if (blockIdx.y == 1) { s = wg; d = dg; }
    else                      { s = wo; d = dw; }
    float4 v = ((const float4*)s)[i];
    uint2 o;
    o.x = pack2h(__float2half_rn(v.x), __float2half_rn(v.y));
    o.y = pack2h(__float2half_rn(v.z), __float2half_rn(v.w));
    ((uint2*)d)[i] = o;
}

// v_weight [4096,2048] -> vt [2048,4096], * SCALE
__global__ void vtrans_kernel(const float* __restrict__ v, __half* __restrict__ t) {
    __shared__ float sm[32][33];
    int c0 = blockIdx.x * 32;
    int m0 = blockIdx.y * 32;
    int tx = threadIdx.x, ty = threadIdx.y;
#pragma unroll
    for (int j = 0; j < 4; j++)
        sm[ty + 8 * j][tx] = v[(size_t)(m0 + ty + 8 * j) * 2048 + c0 + tx] * SCALE_F;
    __syncthreads();
#pragma unroll
    for (int j = 0; j < 4; j++)
        t[(size_t)(c0 + ty + 8 * j) * 4096 + m0 + tx] = __float2half_rn(sm[tx][ty + 8 * j]);
}

// ---------------- warp-MMA GEMM (fp16 single-pass) ----------------
// C[4096x2048] = A[4096x2048] * B[2048x2048]^T, both K-major.
// CTA 128x128, BK=64, 8 warps (2x4), warp 64x32, 3-stage cp.async, 2 CTA/SM.
extern __shared__ __align__(16) char smem_dyn[];

template<int SILU, int HALFOUT>
__global__ __launch_bounds__(256, 2)
void gemm_mma(const __half* __restrict__ A, const __half* __restrict__ Bw,
              float* __restrict__ Cf, __half* __restrict__ Ch) {
    const u32 sb = smem_u32(smem_dyn);
    const int tid = threadIdx.x, lane = tid & 31, wid = tid >> 5;
    const int l7 = lane & 7;
    const int m0 = blockIdx.y * 128, n0 = blockIdx.x * 128;
    const int wm = (wid >> 2) * 64, wn = (wid & 3) * 32;

    float acc[4][4][4];
#pragma unroll
    for (int i = 0; i < 4; i++)
#pragma unroll
        for (int j = 0; j < 4; j++)
#pragma unroll
            for (int c = 0; c < 4; c++) acc[i][j][c] = 0.0f;

    auto issue = [&](int it) {
        const int k0 = it * 64;
        const u32 base = sb + (it % 3) * 32768;
#pragma unroll
        for (int i = 0; i < 8; i++) {
            int f = tid + i * 256;             // 0..2047
            int t = f >> 10, rem = f & 1023;
            int row = rem >> 3, kc = rem & 7;
            const __half* gp = t ? Bw : A;
            int rb = t ? n0 : m0;
            const void* src = gp + (size_t)(rb + row) * 2048 + k0 + kc * 8;
            cpasync16(base + t * 16384 + SWZ((u32)(row * 128 + kc * 16)), src);
        }
    };

    issue(0); CP_COMMIT;
    issue(1); CP_COMMIT;
    for (int it = 0; it < 32; it++) {
        if (it < 30) { CP_WAIT(1); } else { CP_WAIT(0); }
        __syncthreads();
        if (it + 2 < 32) { issue(it + 2); CP_COMMIT; }
        const u32 base = sb + (it % 3) * 32768;
#pragma unroll
        for (int kk = 0; kk < 4; kk++) {
            u32 bh[8];
#pragma unroll
            for (int g = 0; g < 2; g++) {
                int nrow = wn + g * 16 + l7 + ((lane >> 4) & 1) * 8;
                int kb = kk * 32 + ((lane >> 3) & 1) * 16;
                u32 a = base + 16384 + SWZ((u32)(nrow * 128 + kb));
                ldsm4(a, bh[4 * g], bh[4 * g + 1], bh[4 * g + 2], bh[4 * g + 3]);
            }
#pragma unroll
            for (int mf = 0; mf < 4; mf++) {
                int arow = wm + mf * 16 + l7 + ((lane >> 3) & 1) * 8;
                int akb = kk * 32 + ((lane >> 4) & 1) * 16;
                u32 a0, a1, a2, a3;
                ldsm4(base + SWZ((u32)(arow * 128 + akb)), a0, a1, a2, a3);
#pragma unroll
                for (int nf = 0; nf < 4; nf++)
                    mma16816(acc[mf][nf], a0, a1, a2, a3, bh[2 * nf], bh[2 * nf + 1]);
            }
        }
        __syncthreads();
    }

#pragma unroll
    for (int mf = 0; mf < 4; mf++)
#pragma unroll
        for (int nf = 0; nf < 4; nf++) {
            int row = m0 + wm + mf * 16 + (lane >> 2);
            int col = n0 + wn + nf * 8 + 2 * (lane & 3);
#pragma unroll
            for (int half = 0; half < 2; half++) {
                int r = row + half * 8;
                float v0 = acc[mf][nf][2 * half + 0];
                float v1 = acc[mf][nf][2 * half + 1];
                if (SILU) { v0 = silu_f(v0); v1 = silu_f(v1); }
                size_t o = (size_t)r * 2048 + col;
                if (HALFOUT) {
                    *(u32*)(Ch + o) = pack2h(__float2half_rn(v0), __float2half_rn(v1));
                } else {
                    float2 w; w.x = v0; w.y = v1;
                    *(float2*)(Cf + o) = w;
                }
            }
        }
}

// ---------------- fused attention (fp16 single-pass) ----------------
// CTA = (128 q-rows, head, batch), 8 warps x 16 rows, 2 CTA/SM.
__global__ __launch_bounds__(256, 2)
void attn_mma(const __half* __restrict__ Q, const __half* __restrict__ Kw,
              const __half* __restrict__ Vt, const float* __restrict__ Gate,
              __half* __restrict__ O) {
    const u32 sb = smem_u32(smem_dyn);
    const int tid = threadIdx.x, lane = tid & 31, wid = tid >> 5;
    const int l7 = lane & 7;
    const int n0 = blockIdx.x * 128;
    const int h  = blockIdx.y;
    const int b  = blockIdx.z;
    const int m0w = wid * 16;
    const size_t qrow0 = (size_t)(b * 2048 + n0);

    // Q preload: 128 rows x 128 d fp16 = 32KB
#pragma unroll
    for (int i = 0; i < 8; i++) {
        int f = tid + i * 256;             // 0..2047
        int row = f >> 4, dc = f & 15;
        const __half* src = Q + (qrow0 + row) * 2048 + h * 128 + dc * 8;
        u32 off = (u32)((dc >> 3) * 16384) + SWZ((u32)(row * 128 + (dc & 7) * 16));
        *(uint4*)(smem_dyn + off) = *(const uint4*)src;
    }

    float oacc[16][4];
#pragma unroll
    for (int i = 0; i < 16; i++)
#pragma unroll
        for (int c = 0; c < 4; c++) oacc[i][c] = 0.0f;

    auto issue_kv = [&](int t) {
        const int m0k = t * 64;
        const u32 base = sb + 32768 + (t & 1) * 32768;
#pragma unroll
        for (int i = 0; i < 8; i++) {
            int f = tid + i * 256;         // 0..2047
            if (f < 1024) {                // K tile: 64 keys x 128 d
                int key = f >> 4, dc = f & 15;
                const void* src = Kw + (size_t)(m0k + key) * 2048 + h * 128 + dc * 8;
                u32 dst = base + (dc >> 3) * 8192 + SWZ((u32)(key * 128 + (dc & 7) * 16));
                cpasync16(dst, src);
            } else {                       // V tile: 128 dv x 64 keys
                int f2 = f - 1024;
                int dv = f2 >> 3, kc = f2 & 7;
                const void* src = Vt + (size_t)(h * 128 + dv) * 4096 + m0k + kc * 8;
                cpasync16(base + 16384 + SWZ((u32)(dv * 128 + kc * 16)), src);
            }
        }
    };

    issue_kv(0); CP_COMMIT;
#pragma unroll 1
    for (int t = 0; t < 64; t++) {
        if (t < 63) { issue_kv(t + 1); CP_COMMIT; CP_WAIT(1); }
        else        { CP_WAIT(0); }
        __syncthreads();
        const u32 kbase = sb + 32768 + (t & 1) * 32768;

#pragma unroll
        for (int half = 0; half < 2; half++) {     // keys [32*half, 32*half+32)
            float sacc[4][4];
#pragma unroll
            for (int j = 0; j < 4; j++)
#pragma unroll
                for (int c = 0; c < 4; c++) sacc[j][c] = 0.0f;

#pragma unroll
            for (int kk = 0; kk < 8; kk++) {       // d chunks of 16
                u32 bh[8];
#pragma unroll
                for (int g = 0; g < 2; g++) {
                    int nrow = half * 32 + g * 16 + l7 + ((lane >> 4) & 1) * 8;
                    int d0 = kk * 16 + ((lane >> 3) & 1) * 8;
                    u32 a = kbase + (d0 >> 6) * 8192 + SWZ((u32)(nrow * 128 + (d0 & 63) * 2));
                    ldsm4(a, bh[4 * g], bh[4 * g + 1], bh[4 * g + 2], bh[4 * g + 3]);
                }
                int arow = m0w + l7 + ((lane >> 3) & 1) * 8;
                int ad0 = kk * 16 + ((lane >> 4) & 1) * 8;
                u32 qa = sb + (ad0 >> 6) * 16384 + SWZ((u32)(arow * 128 + (ad0 & 63) * 2));
                u32 a0, a1, a2, a3;
                ldsm4(qa, a0, a1, a2, a3);
#pragma unroll
                for (int j = 0; j < 4; j++)
                    mma16816(sacc[j], a0, a1, a2, a3, bh[2 * j], bh[2 * j + 1]);
            }

            // silu -> fp16 P (regs), then P @ V for this half's 2 key-chunks
#pragma unroll
            for (int kk2l = 0; kk2l < 2; kk2l++) {
                int kk2 = half * 2 + kk2l;
                u32 pa[4];
#pragma unroll
                for (int q = 0; q < 4; q++) {
                    const float* src = sacc[2 * kk2l + (q >> 1)];
                    float s0 = silu_f(src[(q & 1) * 2 + 0]);
                    float s1 = silu_f(src[(q & 1) * 2 + 1]);
                    pa[q] = pack2h(__float2half_rn(s0), __float2half_rn(s1));
                }
#pragma unroll
                for (int g = 0; g < 8; g++) {
                    int nrow = g * 16 + l7 + ((lane >> 4) & 1) * 8;
                    int kb = kk2 * 32 + ((lane >> 3) & 1) * 16;
                    u32 va = kbase + 16384 + SWZ((u32)(nrow * 128 + kb));
                    u32 v0, v1, v2, v3;
                    ldsm4(va, v0, v1, v2, v3);
                    mma16816(oacc[2 * g],     pa[0], pa[1], pa[2], pa[3], v0, v1);
                    mma16816(oacc[2 * g + 1], pa[0], pa[1], pa[2], pa[3], v2, v3);
                }
            }
        }
        __syncthreads();
    }

    // epilogue: gate (fp32) + fp16 store
#pragma unroll
    for (int nf = 0; nf < 16; nf++) {
        int col = nf * 8 + 2 * (lane & 3);
        int gcol = h * 128 + col;
#pragma unroll
        for (int half = 0; half < 2; half++) {
            int row = m0w + (lane >> 2) + half * 8;
            size_t o = (qrow0 + row) * 2048 + gcol;
            float2 g = *(const float2*)(Gate + o);
            float v0 = oacc[nf][2 * half + 0] * g.x;
            float v1 = oacc[nf][2 * half + 1] * g.y;
            *(u32*)(O + o) = pack2h(__float2half_rn(v0), __float2half_rn(v1));
        }
    }
}

// ---------------- launch ----------------
#define GETSYMH(var, sym) do { void* _p; cudaGetSymbolAddress(&_p, sym); var = (__half*)_p; } while (0)

extern "C" void kernel_launch(void* const* d_in, const int* in_sizes, int n_in,
                              void* d_out, int out_size) {
    const float* x  = (const float*)d_in[0];
    const float* Wq = (const float*)d_in[1];
    const float* kw = (const float*)d_in[2];
    const float* vw = (const float*)d_in[3];
    const float* Wg = (const float*)d_in[4];
    const float* Wo = (const float*)d_in[5];
    float* out = (float*)d_out;

    __half *xh, *wq, *wg, *wo, *k, *vt, *qp, *ap;
    float* gate;
    GETSYMH(xh, g_x);
    GETSYMH(wq, g_wq); GETSYMH(wg, g_wg); GETSYMH(wo, g_wo);
    GETSYMH(k,  g_k);  GETSYMH(vt, g_vt);
    GETSYMH(qp, g_q);  GETSYMH(ap, g_a);
    { void* _p; cudaGetSymbolAddress(&_p, g_gate); gate = (float*)_p; }

    cudaFuncSetAttribute(gemm_mma<0, 1>, cudaFuncAttributeMaxDynamicSharedMemorySize, 98304);
    cudaFuncSetAttribute(gemm_mma<1, 0>, cudaFuncAttributeMaxDynamicSharedMemorySize, 98304);
    cudaFuncSetAttribute(gemm_mma<0, 0>, cudaFuncAttributeMaxDynamicSharedMemorySize, 98304);
    cudaFuncSetAttribute(attn_mma, cudaFuncAttributeMaxDynamicSharedMemorySize, 98304);

    // [0] activations (x, k*scale): n4=2097152 each, grid.y picks tensor
    conv_act_kernel<<<dim3(8192, 2), 256>>>(x, xh, kw, k);
    // [1] weights (Wq, Wg, Wo): n4=1048576 each
    conv_w_kernel<<<dim3(4096, 3), 256>>>(Wq, wq, Wg, wg, Wo, wo);
    // [2] v transpose + scale
    vtrans_kernel<<<dim3(64, 128), dim3(32, 8)>>>(vw, vt);

    dim3 gg(16, 32);
    // [3] q-GEMM
    gemm_mma<0, 1><<<gg, 256, 98304>>>(xh, wq, nullptr, qp);
    // [4] gate-GEMM (silu, fp32 out)
    gemm_mma<1, 0><<<gg, 256, 98304>>>(xh, wg, gate, nullptr);
    // [5] fused attention (gate applied)  <-- ncu -s 5 capture target
    attn_mma<<<dim3(16, 16, 2), 256, 98304>>>(qp, k, vt, gate, ap);
    // [6] output GEMM
    gemm_mma<0, 0><<<gg, 256, 98304>>>(ap, wo, out, nullptr);
}

// round 8
// speedup vs baseline: 7.5602x; 1.1356x over previous
#include <cuda_runtime.h>
#include <cuda_fp16.h>

typedef unsigned int u32;

#define SCALE_F 11.313708498984761f   // sqrt(128)

// ---------------- scratch (all single fp16; gate fp32) ----------------
static __device__ __half g_x[8388608];
static __device__ __half g_wq[4194304], g_wg[4194304], g_wo[4194304];
static __device__ __half g_k[8388608];
static __device__ __half g_vt[8388608];
static __device__ __half g_q[8388608];
static __device__ float  g_gate[8388608];
static __device__ __half g_a[8388608];

// ---------------- helpers ----------------
__device__ __forceinline__ u32 smem_u32(const void* p) {
    u32 a;
    asm("{ .reg .u64 t; cvta.to.shared.u64 t, %1; cvt.u32.u64 %0, t; }" : "=r"(a) : "l"(p));
    return a;
}
#define SWZ(o) ((o) ^ (((o) >> 3) & 0x70))

__device__ __forceinline__ void ldsm4(u32 addr, u32& r0, u32& r1, u32& r2, u32& r3) {
    asm volatile("ldmatrix.sync.aligned.m8n8.x4.shared.b16 {%0,%1,%2,%3}, [%4];"
                 : "=r"(r0), "=r"(r1), "=r"(r2), "=r"(r3) : "r"(addr));
}
__device__ __forceinline__ void mma16816(float (&d)[4], u32 a0, u32 a1, u32 a2, u32 a3,
                                         u32 b0, u32 b1) {
    asm volatile(
        "mma.sync.aligned.m16n8k16.row.col.f32.f16.f16.f32 "
        "{%0,%1,%2,%3},{%4,%5,%6,%7},{%8,%9},{%0,%1,%2,%3};"
        : "+f"(d[0]), "+f"(d[1]), "+f"(d[2]), "+f"(d[3])
        : "r"(a0), "r"(a1), "r"(a2), "r"(a3), "r"(b0), "r"(b1));
}
__device__ __forceinline__ void cpasync16(u32 dst, const void* src) {
    asm volatile("cp.async.cg.shared.global [%0], [%1], 16;" :: "r"(dst), "l"(src));
}
#define CP_COMMIT asm volatile("cp.async.commit_group;" ::: "memory")
#define CP_WAIT(n) asm volatile("cp.async.wait_group %0;" :: "n"(n) : "memory")

__device__ __forceinline__ float silu_f(float x) {
    float e = __expf(-x);
    float r;
    asm("rcp.approx.f32 %0, %1;" : "=f"(r) : "f"(1.0f + e));
    return x * r;
}
__device__ __forceinline__ u32 pack2h(__half a, __half b) {
    return (u32)__half_as_ushort(a) | ((u32)__half_as_ushort(b) << 16);
}

// ---------------- pre-pass (merged) ----------------
__global__ void conv_act_kernel(const float* __restrict__ x, __half* __restrict__ dx,
                                const float* __restrict__ kw, __half* __restrict__ dk) {
    int i = blockIdx.x * blockDim.x + threadIdx.x;
    if (i >= 2097152) return;
    const float* s;
    __half* d;
    float scale;
    if (blockIdx.y == 0) { s = x;  d = dx; scale = 1.0f; }
    else                 { s = kw; d = dk; scale = SCALE_F; }
    float4 v = ((const float4*)s)[i];
    uint2 o;
    o.x = pack2h(__float2half_rn(v.x * scale), __float2half_rn(v.y * scale));
    o.y = pack2h(__float2half_rn(v.z * scale), __float2half_rn(v.w * scale));
    ((uint2*)d)[i] = o;
}

__global__ void conv_w_kernel(const float* __restrict__ wq, __half* __restrict__ dq,
                              const float* __restrict__ wg, __half* __restrict__ dg,
                              const float* __restrict__ wo, __half* __restrict__ dw) {
    int i = blockIdx.x * blockDim.x + threadIdx.x;
    if (i >= 1048576) return;
    const float* s;
    __half* d;
    if (blockIdx.y == 0)      { s = wq; d = dq; }
    else if (blockIdx.y == 1) { s = wg; d = dg; }
    else                      { s = wo; d = dw; }
    float4 v = ((const float4*)s)[i];
    uint2 o;
    o.x = pack2h(__float2half_rn(v.x), __float2half_rn(v.y));
    o.y = pack2h(__float2half_rn(v.z), __float2half_rn(v.w));
    ((uint2*)d)[i] = o;
}

// v_weight [4096,2048] -> vt [2048,4096], * SCALE
__global__ void vtrans_kernel(const float* __restrict__ v, __half* __restrict__ t) {
    __shared__ float sm[32][33];
    int c0 = blockIdx.x * 32;
    int m0 = blockIdx.y * 32;
    int tx = threadIdx.x, ty = threadIdx.y;
#pragma unroll
    for (int j = 0; j < 4; j++)
        sm[ty + 8 * j][tx] = v[(size_t)(m0 + ty + 8 * j) * 2048 + c0 + tx] * SCALE_F;
    __syncthreads();
#pragma unroll
    for (int j = 0; j < 4; j++)
        t[(size_t)(c0 + ty + 8 * j) * 4096 + m0 + tx] = __float2half_rn(sm[tx][ty + 8 * j]);
}

// ---------------- warp-MMA GEMM (fp16, 3-stage, 1 sync/iter) ----------------
extern __shared__ __align__(16) char smem_dyn[];

template<int SILU, int HALFOUT>
__global__ __launch_bounds__(256, 2)
void gemm_mma(const __half* __restrict__ A, const __half* __restrict__ Bw,
              float* __restrict__ Cf, __half* __restrict__ Ch) {
    const u32 sb = smem_u32(smem_dyn);
    const int tid = threadIdx.x, lane = tid & 31, wid = tid >> 5;
    const int l7 = lane & 7;
    const int m0 = blockIdx.y * 128, n0 = blockIdx.x * 128;
    const int wm = (wid >> 2) * 64, wn = (wid & 3) * 32;

    float acc[4][4][4];
#pragma unroll
    for (int i = 0; i < 4; i++)
#pragma unroll
        for (int j = 0; j < 4; j++)
#pragma unroll
            for (int c = 0; c < 4; c++) acc[i][j][c] = 0.0f;

    auto issue = [&](int it) {
        const int k0 = it * 64;
        const u32 base = sb + (it % 3) * 32768;
#pragma unroll
        for (int i = 0; i < 8; i++) {
            int f = tid + i * 256;             // 0..2047
            int t = f >> 10, rem = f & 1023;
            int row = rem >> 3, kc = rem & 7;
            const __half* gp = t ? Bw : A;
            int rb = t ? n0 : m0;
            const void* src = gp + (size_t)(rb + row) * 2048 + k0 + kc * 8;
            cpasync16(base + t * 16384 + SWZ((u32)(row * 128 + kc * 16)), src);
        }
    };

    issue(0); CP_COMMIT;
    issue(1); CP_COMMIT;
    for (int it = 0; it < 32; it++) {
        if (it < 31) { CP_WAIT(1); } else { CP_WAIT(0); }
        __syncthreads();
        if (it + 2 < 32) { issue(it + 2); CP_COMMIT; }
        const u32 base = sb + (it % 3) * 32768;
#pragma unroll
        for (int kk = 0; kk < 4; kk++) {
            u32 bh[8];
#pragma unroll
            for (int g = 0; g < 2; g++) {
                int nrow = wn + g * 16 + l7 + ((lane >> 4) & 1) * 8;
                int kb = kk * 32 + ((lane >> 3) & 1) * 16;
                u32 a = base + 16384 + SWZ((u32)(nrow * 128 + kb));
                ldsm4(a, bh[4 * g], bh[4 * g + 1], bh[4 * g + 2], bh[4 * g + 3]);
            }
#pragma unroll
            for (int mf = 0; mf < 4; mf++) {
                int arow = wm + mf * 16 + l7 + ((lane >> 3) & 1) * 8;
                int akb = kk * 32 + ((lane >> 4) & 1) * 16;
                u32 a0, a1, a2, a3;
                ldsm4(base + SWZ((u32)(arow * 128 + akb)), a0, a1, a2, a3);
#pragma unroll
                for (int nf = 0; nf < 4; nf++)
                    mma16816(acc[mf][nf], a0, a1, a2, a3, bh[2 * nf], bh[2 * nf + 1]);
            }
        }
    }

#pragma unroll
    for (int mf = 0; mf < 4; mf++)
#pragma unroll
        for (int nf = 0; nf < 4; nf++) {
            int row = m0 + wm + mf * 16 + (lane >> 2);
            int col = n0 + wn + nf * 8 + 2 * (lane & 3);
#pragma unroll
            for (int half = 0; half < 2; half++) {
                int r = row + half * 8;
                float v0 = acc[mf][nf][2 * half + 0];
                float v1 = acc[mf][nf][2 * half + 1];
                if (SILU) { v0 = silu_f(v0); v1 = silu_f(v1); }
                size_t o = (size_t)r * 2048 + col;
                if (HALFOUT) {
                    *(u32*)(Ch + o) = pack2h(__float2half_rn(v0), __float2half_rn(v1));
                } else {
                    float2 w; w.x = v0; w.y = v1;
                    *(float2*)(Cf + o) = w;
                }
            }
        }
}

// ---------------- fused attention (Q in regs, 3-stage KV, 1 sync/iter) ----------------
// CTA = (128 q-rows, head, batch), 8 warps x 16 rows, 2 CTA/SM.
// smem: 3 KV stages x 32K (K 16K as two 8K d-halves, V 16K). Q staged in stage0/1
// area once, moved to registers before the pipeline starts. Total 96K.
__global__ __launch_bounds__(256, 2)
void attn_mma(const __half* __restrict__ Q, const __half* __restrict__ Kw,
              const __half* __restrict__ Vt, const float* __restrict__ Gate,
              __half* __restrict__ O) {
    const u32 sb = smem_u32(smem_dyn);
    const int tid = threadIdx.x, lane = tid & 31, wid = tid >> 5;
    const int l7 = lane & 7;
    const int n0 = blockIdx.x * 128;
    const int h  = blockIdx.y;
    const int b  = blockIdx.z;
    const int m0w = wid * 16;
    const size_t qrow0 = (size_t)(b * 2048 + n0);

    // ---- stage Q (128x128 fp16, 32KB) into [0,32K), then lift to registers
#pragma unroll
    for (int i = 0; i < 8; i++) {
        int f = tid + i * 256;             // 0..2047
        int row = f >> 4, dc = f & 15;
        const __half* src = Q + (qrow0 + row) * 2048 + h * 128 + dc * 8;
        u32 dst = sb + (u32)((dc >> 3) * 16384) + SWZ((u32)(row * 128 + (dc & 7) * 16));
        cpasync16(dst, src);
    }
    CP_COMMIT; CP_WAIT(0);
    __syncthreads();

    u32 qf[8][4];
#pragma unroll
    for (int kk = 0; kk < 8; kk++) {
        int arow = m0w + l7 + ((lane >> 3) & 1) * 8;
        int ad0 = kk * 16 + ((lane >> 4) & 1) * 8;
        u32 qa = sb + (u32)((ad0 >> 6) * 16384) + SWZ((u32)(arow * 128 + (ad0 & 63) * 2));
        ldsm4(qa, qf[kk][0], qf[kk][1], qf[kk][2], qf[kk][3]);
    }
    __syncthreads();   // everyone done reading Q before KV overwrites

    float oacc[16][4];
#pragma unroll
    for (int i = 0; i < 16; i++)
#pragma unroll
        for (int c = 0; c < 4; c++) oacc[i][c] = 0.0f;

    auto issue_kv = [&](int t) {
        const int m0k = t * 64;
        const u32 base = sb + (t % 3) * 32768;
#pragma unroll
        for (int i = 0; i < 8; i++) {
            int f = tid + i * 256;         // 0..2047
            if (f < 1024) {                // K tile: 64 keys x 128 d (two 8K d-halves)
                int key = f >> 4, dc = f & 15;
                const void* src = Kw + (size_t)(m0k + key) * 2048 + h * 128 + dc * 8;
                u32 dst = base + (dc >> 3) * 8192 + SWZ((u32)(key * 128 + (dc & 7) * 16));
                cpasync16(dst, src);
            } else {                       // V tile: 128 dv x 64 keys
                int f2 = f - 1024;
                int dv = f2 >> 3, kc = f2 & 7;
                const void* src = Vt + (size_t)(h * 128 + dv) * 4096 + m0k + kc * 8;
                cpasync16(base + 16384 + SWZ((u32)(dv * 128 + kc * 16)), src);
            }
        }
    };

    issue_kv(0); CP_COMMIT;
    issue_kv(1); CP_COMMIT;
#pragma unroll 1
    for (int t = 0; t < 64; t++) {
        if (t < 63) { CP_WAIT(1); } else { CP_WAIT(0); }
        __syncthreads();
        if (t + 2 < 64) { issue_kv(t + 2); CP_COMMIT; }
        const u32 kbase = sb + (t % 3) * 32768;

#pragma unroll
        for (int half = 0; half < 2; half++) {     // keys [32*half, 32*half+32)
            float sacc[4][4];
#pragma unroll
            for (int j = 0; j < 4; j++)
#pragma unroll
                for (int c = 0; c < 4; c++) sacc[j][c] = 0.0f;

#pragma unroll
            for (int kk = 0; kk < 8; kk++) {       // d chunks of 16
                u32 bh[8];
#pragma unroll
                for (int g = 0; g < 2; g++) {
                    int nrow = half * 32 + g * 16 + l7 + ((lane >> 4) & 1) * 8;
                    int d0 = kk * 16 + ((lane >> 3) & 1) * 8;
                    u32 a = kbase + (d0 >> 6) * 8192 + SWZ((u32)(nrow * 128 + (d0 & 63) * 2));
                    ldsm4(a, bh[4 * g], bh[4 * g + 1], bh[4 * g + 2], bh[4 * g + 3]);
                }
#pragma unroll
                for (int j = 0; j < 4; j++)
                    mma16816(sacc[j], qf[kk][0], qf[kk][1], qf[kk][2], qf[kk][3],
                             bh[2 * j], bh[2 * j + 1]);
            }

            // silu -> fp16 P (regs), then P @ V for this half's 2 key-chunks
#pragma unroll
            for (int kk2l = 0; kk2l < 2; kk2l++) {
                int kk2 = half * 2 + kk2l;
                u32 pa[4];
#pragma unroll
                for (int q = 0; q < 4; q++) {
                    const float* src = sacc[2 * kk2l + (q >> 1)];
                    float s0 = silu_f(src[(q & 1) * 2 + 0]);
                    float s1 = silu_f(src[(q & 1) * 2 + 1]);
                    pa[q] = pack2h(__float2half_rn(s0), __float2half_rn(s1));
                }
#pragma unroll
                for (int g = 0; g < 8; g++) {
                    int nrow = g * 16 + l7 + ((lane >> 4) & 1) * 8;
                    int kb = kk2 * 32 + ((lane >> 3) & 1) * 16;
                    u32 va = kbase + 16384 + SWZ((u32)(nrow * 128 + kb));
                    u32 v0, v1, v2, v3;
                    ldsm4(va, v0, v1, v2, v3);
                    mma16816(oacc[2 * g],     pa[0], pa[1], pa[2], pa[3], v0, v1);
                    mma16816(oacc[2 * g + 1], pa[0], pa[1], pa[2], pa[3], v2, v3);
                }
            }
        }
    }

    // epilogue: gate (fp32) + fp16 store
#pragma unroll
    for (int nf = 0; nf < 16; nf++) {
        int col = nf * 8 + 2 * (lane & 3);
        int gcol = h * 128 + col;
#pragma unroll
        for (int half = 0; half < 2; half++) {
            int row = m0w + (lane >> 2) + half * 8;
            size_t o = (qrow0 + row) * 2048 + gcol;
            float2 g = *(const float2*)(Gate + o);
            float v0 = oacc[nf][2 * half + 0] * g.x;
            float v1 = oacc[nf][2 * half + 1] * g.y;
            *(u32*)(O + o) = pack2h(__float2half_rn(v0), __float2half_rn(v1));
        }
    }
}

// ---------------- launch ----------------
#define GETSYMH(var, sym) do { void* _p; cudaGetSymbolAddress(&_p, sym); var = (__half*)_p; } while (0)

extern "C" void kernel_launch(void* const* d_in, const int* in_sizes, int n_in,
                              void* d_out, int out_size) {
    const float* x  = (const float*)d_in[0];
    const float* Wq = (const float*)d_in[1];
    const float* kw = (const float*)d_in[2];
    const float* vw = (const float*)d_in[3];
    const float* Wg = (const float*)d_in[4];
    const float* Wo = (const float*)d_in[5];
    float* out = (float*)d_out;

    __half *xh, *wq, *wg, *wo, *k, *vt, *qp, *ap;
    float* gate;
    GETSYMH(xh, g_x);
    GETSYMH(wq, g_wq); GETSYMH(wg, g_wg); GETSYMH(wo, g_wo);
    GETSYMH(k,  g_k);  GETSYMH(vt, g_vt);
    GETSYMH(qp, g_q);  GETSYMH(ap, g_a);
    { void* _p; cudaGetSymbolAddress(&_p, g_gate); gate = (float*)_p; }

    cudaFuncSetAttribute(gemm_mma<0, 1>, cudaFuncAttributeMaxDynamicSharedMemorySize, 98304);
    cudaFuncSetAttribute(gemm_mma<1, 0>, cudaFuncAttributeMaxDynamicSharedMemorySize, 98304);
    cudaFuncSetAttribute(gemm_mma<0, 0>, cudaFuncAttributeMaxDynamicSharedMemorySize, 98304);
    cudaFuncSetAttribute(attn_mma, cudaFuncAttributeMaxDynamicSharedMemorySize, 98304);

    conv_act_kernel<<<dim3(8192, 2), 256>>>(x, xh, kw, k);
    conv_w_kernel<<<dim3(4096, 3), 256>>>(Wq, wq, Wg, wg, Wo, wo);
    vtrans_kernel<<<dim3(64, 128), dim3(32, 8)>>>(vw, vt);

    dim3 gg(16, 32);
    gemm_mma<0, 1><<<gg, 256, 98304>>>(xh, wq, nullptr, qp);        // [3] q-GEMM
    gemm_mma<1, 0><<<gg, 256, 98304>>>(xh, wg, gate, nullptr);      // [4] gate-GEMM
    attn_mma<<<dim3(16, 16, 2), 256, 98304>>>(qp, k, vt, gate, ap); // [5] attention
    gemm_mma<0, 0><<<gg, 256, 98304>>>(ap, wo, out, nullptr);       // [6] out-GEMM
}